// round 1
// baseline (speedup 1.0000x reference)
#include <cuda_runtime.h>
#include <math.h>
#include <stdint.h>

// ---------------------------------------------------------------------------
// Problem constants (fixed by the dataset)
// ---------------------------------------------------------------------------
#define N_NODES 20000
#define N_EDGES 320000
#define HIDDEN  128
#define HEADS   8
#define LAYERS  3
#define EXP_DEG 4
#define NV      (N_NODES + 1)            // 20001 nodes incl. virtual node
#define E_LOCAL (N_EDGES + 2 * N_NODES)  // 360000 (edges + vn<->all)
#define E_EXP   (NV * EXP_DEG)           // 80004 per layer

// ---------------------------------------------------------------------------
// Scratch (device globals; no allocations anywhere)
// ---------------------------------------------------------------------------
__device__ float    g_xv  [(size_t)NV * HIDDEN];
__device__ float    g_acc [(size_t)NV * HIDDEN];
__device__ float    g_q   [(size_t)NV * HIDDEN];
__device__ float    g_k   [(size_t)NV * HIDDEN];
__device__ float    g_v   [(size_t)NV * HIDDEN];
__device__ float    g_agg [(size_t)NV * HIDDEN];
__device__ float    g_h1  [(size_t)NV * 4 * HIDDEN];
__device__ float    g_sc  [(size_t)E_LOCAL * HEADS];   // scores / exp-scores
__device__ unsigned g_m   [(size_t)NV * HEADS];        // max keys (encoded)
__device__ float    g_s   [(size_t)NV * HEADS];        // softmax denominators

// ---------------------------------------------------------------------------
// Order-preserving float<->uint mapping for atomicMax on floats
// ---------------------------------------------------------------------------
__device__ __forceinline__ unsigned f2key(float f) {
    unsigned u = __float_as_uint(f);
    return (u & 0x80000000u) ? ~u : (u | 0x80000000u);
}
__device__ __forceinline__ float key2f(unsigned k) {
    unsigned u = (k & 0x80000000u) ? (k & 0x7fffffffu) : ~k;
    return __uint_as_float(u);
}

// ---------------------------------------------------------------------------
// Edge addressing: mode 0 = local (raw edges + virtual-node edges built on
// the fly), mode 1 = explicit src/dst arrays (expander)
// ---------------------------------------------------------------------------
struct EdgeCtx {
    const int* a;   // src array (mode1) / edge_index row0 (mode0)
    const int* b;   // dst array (mode1) / edge_index row1 (mode0)
    int E0;         // raw edge count (mode0)
    int n;          // N_NODES == virtual node id (mode0)
    int E;          // total edges
    int mode;
};

__device__ __forceinline__ void get_edge(const EdgeCtx& c, int e, int& s, int& d) {
    if (c.mode == 0) {
        if (e < c.E0)              { s = c.a[e];          d = c.b[e]; }
        else if (e < c.E0 + c.n)   { s = e - c.E0;        d = c.n;    }
        else                       { s = c.n;             d = e - c.E0 - c.n; }
    } else {
        s = c.a[e]; d = c.b[e];
    }
}

// ---------------------------------------------------------------------------
// Utility kernels (graph-safe replacements for memset/memcpy)
// ---------------------------------------------------------------------------
__global__ void k_zero(float* p, size_t n) {
    size_t i = (size_t)blockIdx.x * blockDim.x + threadIdx.x;
    if (i < n) p[i] = 0.0f;
}
__global__ void k_zero_u(unsigned* p, size_t n) {
    size_t i = (size_t)blockIdx.x * blockDim.x + threadIdx.x;
    if (i < n) p[i] = 0u;   // 0 is the minimum key => identity for atomicMax
}
__global__ void k_copy(float* __restrict__ dst, const float* __restrict__ src, size_t n) {
    size_t i = (size_t)blockIdx.x * blockDim.x + threadIdx.x;
    if (i < n) dst[i] = src[i];
}
__global__ void k_build_xv(const float* __restrict__ x, float* __restrict__ xv) {
    size_t i = (size_t)blockIdx.x * blockDim.x + threadIdx.x;
    size_t tot = (size_t)NV * HIDDEN;
    if (i < tot) xv[i] = (i < (size_t)N_NODES * HIDDEN) ? x[i] : 0.0f;
}

// ---------------------------------------------------------------------------
// SGEMM: C = op(A[M,K] @ B[K,N] + bias)
//   mode 0: C = r
//   mode 1: C += r   (accumulate into existing C)
//   mode 2: C = gelu_exact(r)
// 64x64 tile, BK=16, 256 threads, 4x4 microtile.
// Requires N % 64 == 0, K % 16 == 0 (true here: N in {128,512}, K in {128,512}).
// ---------------------------------------------------------------------------
#define BM 64
#define BN 64
#define BK 16
__global__ __launch_bounds__(256) void k_sgemm(
    const float* __restrict__ A, const float* __restrict__ B,
    const float* __restrict__ bias, float* __restrict__ C,
    int M, int N, int K, int mode)
{
    __shared__ float As[BK][BM];
    __shared__ float Bs[BK][BN];
    const int bm = blockIdx.y * BM;
    const int bn = blockIdx.x * BN;
    const int tid = threadIdx.x;
    const int tx = tid & 15;   // 0..15 -> 4 cols each
    const int ty = tid >> 4;   // 0..15 -> 4 rows each

    float acc[4][4] = {};

    for (int k0 = 0; k0 < K; k0 += BK) {
        // A tile: 64x16, thread loads 4 consecutive elems of one row
        {
            int arow = tid >> 2;
            int acol = (tid & 3) << 2;
            int gr = bm + arow;
            #pragma unroll
            for (int j = 0; j < 4; j++) {
                float v = 0.0f;
                if (gr < M) v = A[(size_t)gr * K + k0 + acol + j];
                As[acol + j][arow] = v;
            }
        }
        // B tile: 16x64
        {
            int brow = tid >> 4;
            int bcol = (tid & 15) << 2;
            const float* bp = B + (size_t)(k0 + brow) * N + bn + bcol;
            #pragma unroll
            for (int j = 0; j < 4; j++) Bs[brow][bcol + j] = bp[j];
        }
        __syncthreads();
        #pragma unroll
        for (int kk = 0; kk < BK; kk++) {
            float a[4], b[4];
            #pragma unroll
            for (int i = 0; i < 4; i++) a[i] = As[kk][ty * 4 + i];
            #pragma unroll
            for (int i = 0; i < 4; i++) b[i] = Bs[kk][tx * 4 + i];
            #pragma unroll
            for (int i = 0; i < 4; i++)
                #pragma unroll
                for (int j = 0; j < 4; j++)
                    acc[i][j] = fmaf(a[i], b[j], acc[i][j]);
        }
        __syncthreads();
    }

    #pragma unroll
    for (int i = 0; i < 4; i++) {
        int r = bm + ty * 4 + i;
        if (r >= M) continue;
        #pragma unroll
        for (int j = 0; j < 4; j++) {
            int c = bn + tx * 4 + j;
            float v = acc[i][j] + bias[c];
            if (mode == 1) {
                v += C[(size_t)r * N + c];
            } else if (mode == 2) {
                v = 0.5f * v * (1.0f + erff(v * 0.70710678118654752440f)); // exact gelu
            }
            C[(size_t)r * N + c] = v;
        }
    }
}

// ---------------------------------------------------------------------------
// Edge pass A: per-edge per-head scores + segment max (one warp per edge)
// ---------------------------------------------------------------------------
__global__ void k_edge_score(const float* __restrict__ q, const float* __restrict__ k,
                             float* __restrict__ scores, unsigned* __restrict__ mkey,
                             EdgeCtx ec)
{
    int e = (blockIdx.x * blockDim.x + threadIdx.x) >> 5;
    int lane = threadIdx.x & 31;
    if (e >= ec.E) return;
    int s, d; get_edge(ec, e, s, d);
    float4 qa = *(const float4*)(q + (size_t)d * HIDDEN + lane * 4);
    float4 ka = *(const float4*)(k + (size_t)s * HIDDEN + lane * 4);
    float dp = qa.x * ka.x + qa.y * ka.y + qa.z * ka.z + qa.w * ka.w;
    dp += __shfl_xor_sync(0xffffffffu, dp, 1);
    dp += __shfl_xor_sync(0xffffffffu, dp, 2);
    int h = lane >> 2;
    if ((lane & 3) == 0) {
        float sc = dp * 0.25f;  // 1/sqrt(16)
        scores[(size_t)e * HEADS + h] = sc;
        atomicMax(&mkey[(size_t)d * HEADS + h], f2key(sc));
    }
}

// ---------------------------------------------------------------------------
// Edge pass B: exp(score - max) + segment sum (one thread per edge-head)
// ---------------------------------------------------------------------------
__global__ void k_edge_exp(float* __restrict__ scores, const unsigned* __restrict__ mkey,
                           float* __restrict__ ssum, EdgeCtx ec)
{
    int idx = blockIdx.x * blockDim.x + threadIdx.x;
    if (idx >= ec.E * HEADS) return;
    int e = idx >> 3, h = idx & 7;
    int s, d; get_edge(ec, e, s, d);
    (void)s;
    float ex = __expf(scores[idx] - key2f(mkey[(size_t)d * HEADS + h]));
    scores[idx] = ex;
    atomicAdd(&ssum[(size_t)d * HEADS + h], ex);
}

// ---------------------------------------------------------------------------
// Edge pass C: agg[dst] += alpha * v[src] (one warp per edge, 4 dims/lane)
// ---------------------------------------------------------------------------
__global__ void k_edge_agg(const float* __restrict__ v, const float* __restrict__ scores,
                           const float* __restrict__ ssum, float* __restrict__ agg,
                           EdgeCtx ec)
{
    int e = (blockIdx.x * blockDim.x + threadIdx.x) >> 5;
    int lane = threadIdx.x & 31;
    if (e >= ec.E) return;
    int s, d; get_edge(ec, e, s, d);
    int h = lane >> 2;
    float alpha = scores[(size_t)e * HEADS + h] / (ssum[(size_t)d * HEADS + h] + 1e-16f);
    float4 va = *(const float4*)(v + (size_t)s * HIDDEN + lane * 4);
    float* ap = agg + (size_t)d * HIDDEN + lane * 4;
    atomicAdd(ap + 0, alpha * va.x);
    atomicAdd(ap + 1, alpha * va.y);
    atomicAdd(ap + 2, alpha * va.z);
    atomicAdd(ap + 3, alpha * va.w);
}

// ---------------------------------------------------------------------------
// LayerNorm: one warp per row of 128
// ---------------------------------------------------------------------------
__global__ void k_layernorm(const float* __restrict__ in, const float* __restrict__ g,
                            const float* __restrict__ b, float* __restrict__ out, int M)
{
    int row = blockIdx.x * (blockDim.x >> 5) + (threadIdx.x >> 5);
    int lane = threadIdx.x & 31;
    if (row >= M) return;
    const float* p = in + (size_t)row * HIDDEN;
    float vals[4], s = 0.0f, s2 = 0.0f;
    #pragma unroll
    for (int i = 0; i < 4; i++) {
        float v = p[lane + i * 32];
        vals[i] = v; s += v; s2 += v * v;
    }
    #pragma unroll
    for (int o = 16; o; o >>= 1) {
        s  += __shfl_xor_sync(0xffffffffu, s,  o);
        s2 += __shfl_xor_sync(0xffffffffu, s2, o);
    }
    float mu  = s * (1.0f / HIDDEN);
    float var = s2 * (1.0f / HIDDEN) - mu * mu;
    float inv = rsqrtf(var + 1e-5f);
    #pragma unroll
    for (int i = 0; i < 4; i++) {
        int c = lane + i * 32;
        out[(size_t)row * HIDDEN + c] = (vals[i] - mu) * inv * g[c] + b[c];
    }
}

// ---------------------------------------------------------------------------
// Host-side orchestration
// ---------------------------------------------------------------------------
static inline dim3 grid1(size_t n, int bs) { return dim3((unsigned)((n + bs - 1) / bs)); }

static void launch_gemm(const float* A, const float* B, const float* bias, float* C,
                        int M, int N, int K, int mode) {
    dim3 g((N + BN - 1) / BN, (M + BM - 1) / BM);
    k_sgemm<<<g, 256>>>(A, B, bias, C, M, N, K, mode);
}

static void run_attention(float* xv, float* acc,
                          float* q, float* k, float* v, float* agg,
                          float* sc, unsigned* mkey, float* ssum,
                          const float* wq, const float* bq,
                          const float* wk, const float* bk,
                          const float* wv, const float* bv,
                          const float* wo, const float* bo,
                          EdgeCtx ec)
{
    launch_gemm(xv, wq, bq, q, NV, HIDDEN, HIDDEN, 0);
    launch_gemm(xv, wk, bk, k, NV, HIDDEN, HIDDEN, 0);
    launch_gemm(xv, wv, bv, v, NV, HIDDEN, HIDDEN, 0);

    k_zero_u<<<grid1((size_t)NV * HEADS, 256), 256>>>(mkey, (size_t)NV * HEADS);
    k_zero  <<<grid1((size_t)NV * HEADS, 256), 256>>>(ssum, (size_t)NV * HEADS);
    k_zero  <<<grid1((size_t)NV * HIDDEN, 256), 256>>>(agg, (size_t)NV * HIDDEN);

    size_t warps = (size_t)ec.E * 32;
    k_edge_score<<<grid1(warps, 256), 256>>>(q, k, sc, mkey, ec);
    k_edge_exp  <<<grid1((size_t)ec.E * HEADS, 256), 256>>>(sc, mkey, ssum, ec);
    k_edge_agg  <<<grid1(warps, 256), 256>>>(v, sc, ssum, agg, ec);

    // acc += agg @ wo + bo
    launch_gemm(agg, wo, bo, acc, NV, HIDDEN, HIDDEN, 1);
}

extern "C" void kernel_launch(void* const* d_in, const int* in_sizes, int n_in,
                              void* d_out, int out_size)
{
    (void)n_in; (void)in_sizes; (void)out_size;
    // Inputs in metadata order
    const float* x         = (const float*)d_in[0];
    const int*   edge_idx  = (const int*)  d_in[1];
    const int*   exp_edges = (const int*)  d_in[2];
    const float* lq_w = (const float*)d_in[3];   const float* lq_b = (const float*)d_in[4];
    const float* lk_w = (const float*)d_in[5];   const float* lk_b = (const float*)d_in[6];
    const float* lv_w = (const float*)d_in[7];   const float* lv_b = (const float*)d_in[8];
    const float* lo_w = (const float*)d_in[9];   const float* lo_b = (const float*)d_in[10];
    const float* eq_w = (const float*)d_in[11];  const float* eq_b = (const float*)d_in[12];
    const float* ek_w = (const float*)d_in[13];  const float* ek_b = (const float*)d_in[14];
    const float* ev_w = (const float*)d_in[15];  const float* ev_b = (const float*)d_in[16];
    const float* eo_w = (const float*)d_in[17];  const float* eo_b = (const float*)d_in[18];
    const float* ln_g = (const float*)d_in[19];  const float* ln_b = (const float*)d_in[20];
    const float* ffn_w1 = (const float*)d_in[21]; const float* ffn_b1 = (const float*)d_in[22];
    const float* ffn_w2 = (const float*)d_in[23]; const float* ffn_b2 = (const float*)d_in[24];

    // Resolve scratch symbol addresses (capture-safe, no allocation)
    float *xv, *acc, *q, *k, *v, *agg, *h1, *sc, *ssum; unsigned* mkey;
    cudaGetSymbolAddress((void**)&xv,   g_xv);
    cudaGetSymbolAddress((void**)&acc,  g_acc);
    cudaGetSymbolAddress((void**)&q,    g_q);
    cudaGetSymbolAddress((void**)&k,    g_k);
    cudaGetSymbolAddress((void**)&v,    g_v);
    cudaGetSymbolAddress((void**)&agg,  g_agg);
    cudaGetSymbolAddress((void**)&h1,   g_h1);
    cudaGetSymbolAddress((void**)&sc,   g_sc);
    cudaGetSymbolAddress((void**)&mkey, g_m);
    cudaGetSymbolAddress((void**)&ssum, g_s);

    const size_t nvh = (size_t)NV * HIDDEN;

    // xv = [x; 0]
    k_build_xv<<<grid1(nvh, 256), 256>>>(x, xv);

    for (int l = 0; l < LAYERS; l++) {
        // acc = residual
        k_copy<<<grid1(nvh, 256), 256>>>(acc, xv, nvh);

        // local attention (raw edges + virtual-node edges)
        EdgeCtx ec_local;
        ec_local.a = edge_idx; ec_local.b = edge_idx + N_EDGES;
        ec_local.E0 = N_EDGES; ec_local.n = N_NODES;
        ec_local.E = E_LOCAL;  ec_local.mode = 0;
        run_attention(xv, acc, q, k, v, agg, sc, mkey, ssum,
                      lq_w + (size_t)l * HIDDEN * HIDDEN, lq_b + (size_t)l * HIDDEN,
                      lk_w + (size_t)l * HIDDEN * HIDDEN, lk_b + (size_t)l * HIDDEN,
                      lv_w + (size_t)l * HIDDEN * HIDDEN, lv_b + (size_t)l * HIDDEN,
                      lo_w + (size_t)l * HIDDEN * HIDDEN, lo_b + (size_t)l * HIDDEN,
                      ec_local);

        // expander attention
        EdgeCtx ec_exp;
        ec_exp.a = exp_edges + (size_t)l * 2 * E_EXP;
        ec_exp.b = ec_exp.a + E_EXP;
        ec_exp.E0 = 0; ec_exp.n = N_NODES;
        ec_exp.E = E_EXP; ec_exp.mode = 1;
        run_attention(xv, acc, q, k, v, agg, sc, mkey, ssum,
                      eq_w + (size_t)l * HIDDEN * HIDDEN, eq_b + (size_t)l * HIDDEN,
                      ek_w + (size_t)l * HIDDEN * HIDDEN, ek_b + (size_t)l * HIDDEN,
                      ev_w + (size_t)l * HIDDEN * HIDDEN, ev_b + (size_t)l * HIDDEN,
                      eo_w + (size_t)l * HIDDEN * HIDDEN, eo_b + (size_t)l * HIDDEN,
                      ec_exp);

        // xv = LN(acc)
        {
            int warps_per_block = 8; // 256 threads
            dim3 g((NV + warps_per_block - 1) / warps_per_block);
            k_layernorm<<<g, warps_per_block * 32>>>(acc, ln_g + (size_t)l * HIDDEN,
                                                     ln_b + (size_t)l * HIDDEN, xv, NV);
        }

        // FFN: h1 = gelu(xv@w1+b1); xv += h1@w2+b2
        launch_gemm(xv, ffn_w1 + (size_t)l * HIDDEN * 4 * HIDDEN,
                    ffn_b1 + (size_t)l * 4 * HIDDEN, h1, NV, 4 * HIDDEN, HIDDEN, 2);
        launch_gemm(h1, ffn_w2 + (size_t)l * 4 * HIDDEN * HIDDEN,
                    ffn_b2 + (size_t)l * HIDDEN, xv, NV, HIDDEN, 4 * HIDDEN, 1);
    }

    // out = xv[:N_NODES]
    k_copy<<<grid1((size_t)N_NODES * HIDDEN, 256), 256>>>((float*)d_out, xv,
                                                          (size_t)N_NODES * HIDDEN);
}

// round 2
// speedup vs baseline: 1.8512x; 1.8512x over previous
#include <cuda_runtime.h>
#include <math.h>
#include <stdint.h>

// ---------------------------------------------------------------------------
// Problem constants
// ---------------------------------------------------------------------------
#define N_NODES 20000
#define N_EDGES 320000
#define HIDDEN  128
#define HEADS   8
#define LAYERS  3
#define EXP_DEG 4
#define NV      (N_NODES + 1)
#define E_LOCAL (N_EDGES + 2 * N_NODES)  // 360000
#define E_EXP   (NV * EXP_DEG)           // 80004

// ---------------------------------------------------------------------------
// Scratch (device globals; no allocations)
// ---------------------------------------------------------------------------
__device__ float g_xv  [(size_t)NV * HIDDEN];
__device__ float g_acc [(size_t)NV * HIDDEN];
__device__ float g_q   [(size_t)NV * HIDDEN];
__device__ float g_k   [(size_t)NV * HIDDEN];
__device__ float g_v   [(size_t)NV * HIDDEN];
__device__ float g_agg [(size_t)NV * HIDDEN];
__device__ float g_h1  [(size_t)NV * 4 * HIDDEN];
__device__ float g_sc  [(size_t)E_LOCAL * HEADS];   // exp(scores)
__device__ float g_s   [(size_t)NV * HEADS];        // softmax denominators

// ---------------------------------------------------------------------------
// Edge addressing
// ---------------------------------------------------------------------------
struct EdgeCtx {
    const int* a;
    const int* b;
    int E0;     // raw edge count (mode0)
    int n;      // virtual node id (mode0)
    int E;
    int mode;   // 0 = local (synth vn edges), 1 = explicit arrays
};

__device__ __forceinline__ void get_edge(const EdgeCtx& c, int e, int& s, int& d) {
    if (c.mode == 0) {
        if (e < c.E0)            { s = c.a[e];   d = c.b[e]; }
        else if (e < c.E0 + c.n) { s = e - c.E0; d = c.n;    }
        else                     { s = c.n;      d = e - c.E0 - c.n; }
    } else {
        s = c.a[e]; d = c.b[e];
    }
}

// ---------------------------------------------------------------------------
// Utility kernels
// ---------------------------------------------------------------------------
__global__ void k_zero(float* p, size_t n) {
    size_t i = (size_t)blockIdx.x * blockDim.x + threadIdx.x;
    if (i < n) p[i] = 0.0f;
}
__global__ void k_copy4(float4* __restrict__ dst, const float4* __restrict__ src, size_t n4) {
    size_t i = (size_t)blockIdx.x * blockDim.x + threadIdx.x;
    if (i < n4) dst[i] = src[i];
}
__global__ void k_build_xv(const float4* __restrict__ x, float4* __restrict__ xv) {
    size_t i = (size_t)blockIdx.x * blockDim.x + threadIdx.x;
    size_t tot = (size_t)NV * HIDDEN / 4;
    size_t lim = (size_t)N_NODES * HIDDEN / 4;
    if (i < tot) xv[i] = (i < lim) ? x[i] : make_float4(0.f, 0.f, 0.f, 0.f);
}

// ---------------------------------------------------------------------------
// SGEMM: r = A[M,K] @ B[K,N] + bias
//   mode 0: C = r
//   mode 1: C += r
//   mode 2: C = gelu_exact(r)
//   mode 3: C = R + r     (residual from separate array)
// BM=128, BN=64, BK=8, 256 threads, 8x4 microtile.
// Requires N % 64 == 0, K % 8 == 0 (N in {128,512}, K in {128,512}).
// ---------------------------------------------------------------------------
#define BM 128
#define BN 64
#define BK 8
#define TM 8
#define TN 4

__global__ __launch_bounds__(256) void k_sgemm(
    const float* __restrict__ A, const float* __restrict__ B,
    const float* __restrict__ bias, float* __restrict__ C,
    const float* __restrict__ R,
    int M, int N, int K, int mode)
{
    __shared__ float As[BK][BM];
    __shared__ float Bs[BK][BN];

    const int bm  = blockIdx.y * BM;
    const int bn  = blockIdx.x * BN;
    const int tid = threadIdx.x;
    const int tx  = tid & 15;    // col group (0..15) -> 4 cols
    const int ty  = tid >> 4;    // row group (0..15) -> 8 rows

    // A tile load: 128 rows x 8 cols, 2 threads/row, float4 each
    const int ar = tid >> 1;
    const int ac = (tid & 1) << 2;
    // B tile load: 8 rows x 64 cols, float2 each
    const int br = tid >> 5;
    const int bc = (tid & 31) << 1;

    const bool arow_ok = (bm + ar) < M;
    const float* Aptr = A + (size_t)(bm + ar) * K + ac;
    const float* Bptr = B + (size_t)br * N + bn + bc;

    float acc[TM][TN];
    #pragma unroll
    for (int i = 0; i < TM; i++)
        #pragma unroll
        for (int j = 0; j < TN; j++) acc[i][j] = 0.0f;

    for (int k0 = 0; k0 < K; k0 += BK) {
        float4 av = make_float4(0.f, 0.f, 0.f, 0.f);
        if (arow_ok) av = *(const float4*)(Aptr + k0);
        As[ac + 0][ar] = av.x;
        As[ac + 1][ar] = av.y;
        As[ac + 2][ar] = av.z;
        As[ac + 3][ar] = av.w;

        float2 bv = *(const float2*)(Bptr + (size_t)k0 * N);
        Bs[br][bc]     = bv.x;
        Bs[br][bc + 1] = bv.y;
        __syncthreads();

        #pragma unroll
        for (int kk = 0; kk < BK; kk++) {
            float a[TM], b[TN];
            #pragma unroll
            for (int i = 0; i < TM; i++) a[i] = As[kk][ty * TM + i];
            #pragma unroll
            for (int j = 0; j < TN; j++) b[j] = Bs[kk][tx * TN + j];
            #pragma unroll
            for (int i = 0; i < TM; i++)
                #pragma unroll
                for (int j = 0; j < TN; j++)
                    acc[i][j] = fmaf(a[i], b[j], acc[i][j]);
        }
        __syncthreads();
    }

    const int cbase = bn + tx * TN;
    float bv0 = bias[cbase + 0], bv1 = bias[cbase + 1];
    float bv2 = bias[cbase + 2], bv3 = bias[cbase + 3];

    #pragma unroll
    for (int i = 0; i < TM; i++) {
        int r = bm + ty * TM + i;
        if (r >= M) continue;
        float* cp = C + (size_t)r * N + cbase;
        float v0 = acc[i][0] + bv0;
        float v1 = acc[i][1] + bv1;
        float v2 = acc[i][2] + bv2;
        float v3 = acc[i][3] + bv3;
        if (mode == 1) {
            float4 old = *(const float4*)cp;
            v0 += old.x; v1 += old.y; v2 += old.z; v3 += old.w;
        } else if (mode == 2) {
            v0 = 0.5f * v0 * (1.0f + erff(v0 * 0.70710678118654752440f));
            v1 = 0.5f * v1 * (1.0f + erff(v1 * 0.70710678118654752440f));
            v2 = 0.5f * v2 * (1.0f + erff(v2 * 0.70710678118654752440f));
            v3 = 0.5f * v3 * (1.0f + erff(v3 * 0.70710678118654752440f));
        } else if (mode == 3) {
            const float4 rr = *(const float4*)(R + (size_t)r * N + cbase);
            v0 += rr.x; v1 += rr.y; v2 += rr.z; v3 += rr.w;
        }
        *(float4*)cp = make_float4(v0, v1, v2, v3);
    }
}

// ---------------------------------------------------------------------------
// Edge pass A: per-edge per-head exp(score) + segment sum (no max pass —
// softmax(s) == exp(s)/sum(exp(s)); scores bounded far below overflow)
// ---------------------------------------------------------------------------
__global__ void k_edge_score(const float* __restrict__ q, const float* __restrict__ k,
                             float* __restrict__ escore, float* __restrict__ ssum,
                             EdgeCtx ec)
{
    int e = (blockIdx.x * blockDim.x + threadIdx.x) >> 5;
    int lane = threadIdx.x & 31;
    if (e >= ec.E) return;
    int s, d; get_edge(ec, e, s, d);
    float4 qa = *(const float4*)(q + (size_t)d * HIDDEN + lane * 4);
    float4 ka = *(const float4*)(k + (size_t)s * HIDDEN + lane * 4);
    float dp = qa.x * ka.x + qa.y * ka.y + qa.z * ka.z + qa.w * ka.w;
    dp += __shfl_xor_sync(0xffffffffu, dp, 1);
    dp += __shfl_xor_sync(0xffffffffu, dp, 2);
    if ((lane & 3) == 0) {
        int h = lane >> 2;
        float ex = __expf(dp * 0.25f);     // scale = 1/sqrt(16)
        escore[(size_t)e * HEADS + h] = ex;
        atomicAdd(&ssum[(size_t)d * HEADS + h], ex);
    }
}

// ---------------------------------------------------------------------------
// Edge pass C: agg[dst] += alpha * v[src]  (vector red.global.add.v4.f32)
// ---------------------------------------------------------------------------
__device__ __forceinline__ void red_add_v4(float* p, float x, float y, float z, float w) {
#if __CUDA_ARCH__ >= 900
    asm volatile("red.global.add.v4.f32 [%0], {%1, %2, %3, %4};"
                 :: "l"(p), "f"(x), "f"(y), "f"(z), "f"(w) : "memory");
#else
    atomicAdd(p + 0, x); atomicAdd(p + 1, y);
    atomicAdd(p + 2, z); atomicAdd(p + 3, w);
#endif
}

__global__ void k_edge_agg(const float* __restrict__ v, const float* __restrict__ escore,
                           const float* __restrict__ ssum, float* __restrict__ agg,
                           EdgeCtx ec)
{
    int e = (blockIdx.x * blockDim.x + threadIdx.x) >> 5;
    int lane = threadIdx.x & 31;
    if (e >= ec.E) return;
    int s, d; get_edge(ec, e, s, d);
    int h = lane >> 2;
    float alpha = escore[(size_t)e * HEADS + h] / (ssum[(size_t)d * HEADS + h] + 1e-16f);
    float4 va = *(const float4*)(v + (size_t)s * HIDDEN + lane * 4);
    red_add_v4(agg + (size_t)d * HIDDEN + lane * 4,
               alpha * va.x, alpha * va.y, alpha * va.z, alpha * va.w);
}

// ---------------------------------------------------------------------------
// LayerNorm: one warp per row of 128
// ---------------------------------------------------------------------------
__global__ void k_layernorm(const float* __restrict__ in, const float* __restrict__ g,
                            const float* __restrict__ b, float* __restrict__ out, int M)
{
    int row = blockIdx.x * (blockDim.x >> 5) + (threadIdx.x >> 5);
    int lane = threadIdx.x & 31;
    if (row >= M) return;
    const float* p = in + (size_t)row * HIDDEN;
    float vals[4], s = 0.0f, s2 = 0.0f;
    #pragma unroll
    for (int i = 0; i < 4; i++) {
        float v = p[lane + i * 32];
        vals[i] = v; s += v; s2 += v * v;
    }
    #pragma unroll
    for (int o = 16; o; o >>= 1) {
        s  += __shfl_xor_sync(0xffffffffu, s,  o);
        s2 += __shfl_xor_sync(0xffffffffu, s2, o);
    }
    float mu  = s * (1.0f / HIDDEN);
    float var = s2 * (1.0f / HIDDEN) - mu * mu;
    float inv = rsqrtf(var + 1e-5f);
    #pragma unroll
    for (int i = 0; i < 4; i++) {
        int c = lane + i * 32;
        out[(size_t)row * HIDDEN + c] = (vals[i] - mu) * inv * g[c] + b[c];
    }
}

// ---------------------------------------------------------------------------
// Host-side orchestration
// ---------------------------------------------------------------------------
static inline dim3 grid1(size_t n, int bs) { return dim3((unsigned)((n + bs - 1) / bs)); }

static void launch_gemm(const float* A, const float* B, const float* bias, float* C,
                        const float* R, int M, int N, int K, int mode) {
    dim3 g(N / BN, (M + BM - 1) / BM);
    k_sgemm<<<g, 256>>>(A, B, bias, C, R, M, N, K, mode);
}

static void run_attention(const float* xv, float* acc,
                          float* q, float* k, float* v, float* agg,
                          float* sc, float* ssum,
                          const float* wq, const float* bq,
                          const float* wk, const float* bk,
                          const float* wv, const float* bv,
                          const float* wo, const float* bo,
                          EdgeCtx ec, int omode)
{
    launch_gemm(xv, wq, bq, q, nullptr, NV, HIDDEN, HIDDEN, 0);
    launch_gemm(xv, wk, bk, k, nullptr, NV, HIDDEN, HIDDEN, 0);
    launch_gemm(xv, wv, bv, v, nullptr, NV, HIDDEN, HIDDEN, 0);

    k_zero<<<grid1((size_t)NV * HEADS, 256), 256>>>(ssum, (size_t)NV * HEADS);
    k_zero<<<grid1((size_t)NV * HIDDEN, 256), 256>>>(agg, (size_t)NV * HIDDEN);

    size_t thr = (size_t)ec.E * 32;
    k_edge_score<<<grid1(thr, 256), 256>>>(q, k, sc, ssum, ec);
    k_edge_agg  <<<grid1(thr, 256), 256>>>(v, sc, ssum, agg, ec);

    // omode 3: acc = xv + (agg@wo+bo);  omode 1: acc += agg@wo+bo
    launch_gemm(agg, wo, bo, acc, xv, NV, HIDDEN, HIDDEN, omode);
}

extern "C" void kernel_launch(void* const* d_in, const int* in_sizes, int n_in,
                              void* d_out, int out_size)
{
    (void)n_in; (void)in_sizes; (void)out_size;
    const float* x         = (const float*)d_in[0];
    const int*   edge_idx  = (const int*)  d_in[1];
    const int*   exp_edges = (const int*)  d_in[2];
    const float* lq_w = (const float*)d_in[3];   const float* lq_b = (const float*)d_in[4];
    const float* lk_w = (const float*)d_in[5];   const float* lk_b = (const float*)d_in[6];
    const float* lv_w = (const float*)d_in[7];   const float* lv_b = (const float*)d_in[8];
    const float* lo_w = (const float*)d_in[9];   const float* lo_b = (const float*)d_in[10];
    const float* eq_w = (const float*)d_in[11];  const float* eq_b = (const float*)d_in[12];
    const float* ek_w = (const float*)d_in[13];  const float* ek_b = (const float*)d_in[14];
    const float* ev_w = (const float*)d_in[15];  const float* ev_b = (const float*)d_in[16];
    const float* eo_w = (const float*)d_in[17];  const float* eo_b = (const float*)d_in[18];
    const float* ln_g = (const float*)d_in[19];  const float* ln_b = (const float*)d_in[20];
    const float* ffn_w1 = (const float*)d_in[21]; const float* ffn_b1 = (const float*)d_in[22];
    const float* ffn_w2 = (const float*)d_in[23]; const float* ffn_b2 = (const float*)d_in[24];

    float *xv, *acc, *q, *k, *v, *agg, *h1, *sc, *ssum;
    cudaGetSymbolAddress((void**)&xv,   g_xv);
    cudaGetSymbolAddress((void**)&acc,  g_acc);
    cudaGetSymbolAddress((void**)&q,    g_q);
    cudaGetSymbolAddress((void**)&k,    g_k);
    cudaGetSymbolAddress((void**)&v,    g_v);
    cudaGetSymbolAddress((void**)&agg,  g_agg);
    cudaGetSymbolAddress((void**)&h1,   g_h1);
    cudaGetSymbolAddress((void**)&sc,   g_sc);
    cudaGetSymbolAddress((void**)&ssum, g_s);

    const size_t nvh = (size_t)NV * HIDDEN;

    k_build_xv<<<grid1(nvh / 4, 256), 256>>>((const float4*)x, (float4*)xv);

    for (int l = 0; l < LAYERS; l++) {
        // local attention: acc = xv + local(xv)
        EdgeCtx ec_local;
        ec_local.a = edge_idx; ec_local.b = edge_idx + N_EDGES;
        ec_local.E0 = N_EDGES; ec_local.n = N_NODES;
        ec_local.E = E_LOCAL;  ec_local.mode = 0;
        run_attention(xv, acc, q, k, v, agg, sc, ssum,
                      lq_w + (size_t)l * HIDDEN * HIDDEN, lq_b + (size_t)l * HIDDEN,
                      lk_w + (size_t)l * HIDDEN * HIDDEN, lk_b + (size_t)l * HIDDEN,
                      lv_w + (size_t)l * HIDDEN * HIDDEN, lv_b + (size_t)l * HIDDEN,
                      lo_w + (size_t)l * HIDDEN * HIDDEN, lo_b + (size_t)l * HIDDEN,
                      ec_local, /*omode=*/3);

        // expander attention: acc += exp(xv)
        EdgeCtx ec_exp;
        ec_exp.a = exp_edges + (size_t)l * 2 * E_EXP;
        ec_exp.b = ec_exp.a + E_EXP;
        ec_exp.E0 = 0; ec_exp.n = N_NODES;
        ec_exp.E = E_EXP; ec_exp.mode = 1;
        run_attention(xv, acc, q, k, v, agg, sc, ssum,
                      eq_w + (size_t)l * HIDDEN * HIDDEN, eq_b + (size_t)l * HIDDEN,
                      ek_w + (size_t)l * HIDDEN * HIDDEN, ek_b + (size_t)l * HIDDEN,
                      ev_w + (size_t)l * HIDDEN * HIDDEN, ev_b + (size_t)l * HIDDEN,
                      eo_w + (size_t)l * HIDDEN * HIDDEN, eo_b + (size_t)l * HIDDEN,
                      ec_exp, /*omode=*/1);

        // xv = LN(acc)
        {
            int wpb = 8;
            dim3 g((NV + wpb - 1) / wpb);
            k_layernorm<<<g, wpb * 32>>>(acc, ln_g + (size_t)l * HIDDEN,
                                         ln_b + (size_t)l * HIDDEN, xv, NV);
        }

        // FFN
        launch_gemm(xv, ffn_w1 + (size_t)l * HIDDEN * 4 * HIDDEN,
                    ffn_b1 + (size_t)l * 4 * HIDDEN, h1, nullptr,
                    NV, 4 * HIDDEN, HIDDEN, 2);
        launch_gemm(h1, ffn_w2 + (size_t)l * 4 * HIDDEN * HIDDEN,
                    ffn_b2 + (size_t)l * HIDDEN, xv, nullptr,
                    NV, HIDDEN, 4 * HIDDEN, 1);
    }

    k_copy4<<<grid1((size_t)N_NODES * HIDDEN / 4, 256), 256>>>(
        (float4*)d_out, (const float4*)xv, (size_t)N_NODES * HIDDEN / 4);
}

// round 3
// speedup vs baseline: 2.3831x; 1.2873x over previous
#include <cuda_runtime.h>
#include <cuda_bf16.h>
#include <math.h>
#include <stdint.h>

// ---------------------------------------------------------------------------
// Problem constants
// ---------------------------------------------------------------------------
#define N_NODES 20000
#define N_EDGES 320000
#define HIDDEN  128
#define HEADS   8
#define LAYERS  3
#define NV      (N_NODES + 1)
#define E_LOCAL (N_EDGES + 2 * N_NODES)  // 360000
#define E_EXP   (NV * 4)                 // 80004
#define QKVN    (3 * HIDDEN)             // 384

// ---------------------------------------------------------------------------
// Scratch (device globals; no allocations)
// ---------------------------------------------------------------------------
__device__ float g_xv   [(size_t)NV * HIDDEN];
__device__ float g_acc  [(size_t)NV * HIDDEN];
__device__ float g_qkv  [(size_t)NV * QKVN];
__device__ float g_agg  [(size_t)NV * HIDDEN];
__device__ float g_h1   [(size_t)NV * 4 * HIDDEN];
__device__ float g_sc   [(size_t)E_LOCAL * HEADS];
__device__ float g_s    [(size_t)NV * HEADS];
__device__ float g_wqkv [(size_t)HIDDEN * QKVN];
__device__ float g_bqkv [QKVN];

// ---------------------------------------------------------------------------
// Edge addressing
// ---------------------------------------------------------------------------
struct EdgeCtx {
    const int* a;
    const int* b;
    int E0;
    int n;
    int E;
    int mode;
};

__device__ __forceinline__ void get_edge(const EdgeCtx& c, int e, int& s, int& d) {
    if (c.mode == 0) {
        if (e < c.E0)            { s = c.a[e];   d = c.b[e]; }
        else if (e < c.E0 + c.n) { s = e - c.E0; d = c.n;    }
        else                     { s = c.n;      d = e - c.E0 - c.n; }
    } else {
        s = c.a[e]; d = c.b[e];
    }
}

// ---------------------------------------------------------------------------
// Utility kernels
// ---------------------------------------------------------------------------
__global__ void k_zero(float* p, size_t n) {
    size_t i = (size_t)blockIdx.x * blockDim.x + threadIdx.x;
    if (i < n) p[i] = 0.0f;
}
__global__ void k_copy4(float4* __restrict__ dst, const float4* __restrict__ src, size_t n4) {
    size_t i = (size_t)blockIdx.x * blockDim.x + threadIdx.x;
    if (i < n4) dst[i] = src[i];
}
__global__ void k_build_xv(const float4* __restrict__ x, float4* __restrict__ xv) {
    size_t i = (size_t)blockIdx.x * blockDim.x + threadIdx.x;
    size_t tot = (size_t)NV * HIDDEN / 4;
    size_t lim = (size_t)N_NODES * HIDDEN / 4;
    if (i < tot) xv[i] = (i < lim) ? x[i] : make_float4(0.f, 0.f, 0.f, 0.f);
}
// pack wq|wk|wv [128,128] each -> [128,384] column-concatenated (+ biases)
__global__ void k_pack_qkv(const float* __restrict__ wq, const float* __restrict__ wk,
                           const float* __restrict__ wv, const float* __restrict__ bq,
                           const float* __restrict__ bk, const float* __restrict__ bv,
                           float* __restrict__ wout, float* __restrict__ bout) {
    int i = blockIdx.x * blockDim.x + threadIdx.x;
    if (i < HIDDEN * QKVN) {
        int k = i / QKVN, n = i % QKVN;
        const float* src = (n < 128) ? wq : (n < 256 ? wk : wv);
        wout[i] = src[k * HIDDEN + (n & 127)];
    }
    if (i < QKVN) {
        const float* bs = (i < 128) ? bq : (i < 256 ? bk : bv);
        bout[i] = bs[i & 127];
    }
}

// ---------------------------------------------------------------------------
// Tensor-core GEMM (bf16 hi/lo split, fp32 accumulate):
//   r = A[M,K] @ B[K,N] + bias
//   mode 0: C = r;  mode 1: C += r;  mode 2: C = gelu(r);  mode 3: C = R + r
// BM=BN=128, BK=32; 256 threads = 8 warps in 4x2; warp tile 32x64.
// A@B ~= Ahi@Bhi + Ahi@Blo + Alo@Bhi   (rel err ~2^-16)
// Requires K % 32 == 0, N % 128 == 0.
// ---------------------------------------------------------------------------
#define BM 128
#define BN 128
#define BK 32
#define APAD 8
#define BPAD 8

__device__ __forceinline__ void ldsm_x4(uint32_t* r, const void* p) {
    uint32_t a = (uint32_t)__cvta_generic_to_shared(p);
    asm volatile("ldmatrix.sync.aligned.m8n8.x4.shared.b16 {%0,%1,%2,%3}, [%4];"
                 : "=r"(r[0]), "=r"(r[1]), "=r"(r[2]), "=r"(r[3]) : "r"(a));
}
__device__ __forceinline__ void ldsm_x4t(uint32_t* r, const void* p) {
    uint32_t a = (uint32_t)__cvta_generic_to_shared(p);
    asm volatile("ldmatrix.sync.aligned.m8n8.x4.trans.shared.b16 {%0,%1,%2,%3}, [%4];"
                 : "=r"(r[0]), "=r"(r[1]), "=r"(r[2]), "=r"(r[3]) : "r"(a));
}
__device__ __forceinline__ void mma_bf16(float* c, const uint32_t* a, const uint32_t* b) {
    asm volatile("mma.sync.aligned.m16n8k16.row.col.f32.bf16.bf16.f32 "
                 "{%0,%1,%2,%3}, {%4,%5,%6,%7}, {%8,%9}, {%0,%1,%2,%3};"
                 : "+f"(c[0]), "+f"(c[1]), "+f"(c[2]), "+f"(c[3])
                 : "r"(a[0]), "r"(a[1]), "r"(a[2]), "r"(a[3]), "r"(b[0]), "r"(b[1]));
}
__device__ __forceinline__ void split2(float x, __nv_bfloat16& h, __nv_bfloat16& l) {
    h = __float2bfloat16_rn(x);
    l = __float2bfloat16_rn(x - __bfloat162float(h));
}

__global__ __launch_bounds__(256) void k_hgemm(
    const float* __restrict__ A, const float* __restrict__ B,
    const float* __restrict__ bias, float* __restrict__ C,
    const float* __restrict__ R,
    int M, int N, int K, int mode)
{
    __shared__ __align__(16) __nv_bfloat16 Ahi[BM][BK + APAD];
    __shared__ __align__(16) __nv_bfloat16 Alo[BM][BK + APAD];
    __shared__ __align__(16) __nv_bfloat16 Bhi[BK][BN + BPAD];
    __shared__ __align__(16) __nv_bfloat16 Blo[BK][BN + BPAD];

    const int bm = blockIdx.y * BM;
    const int bn = blockIdx.x * BN;
    const int tid = threadIdx.x;
    const int lane = tid & 31;
    const int w = tid >> 5;
    const int wm = w & 3;        // warp M index (0..3) -> 32 rows
    const int wn = w >> 2;       // warp N index (0..1) -> 64 cols

    // global-load indexing
    const int ar0 = tid >> 3;          // 0..31 (rows, 4 passes of 32)
    const int ac  = (tid & 7) << 2;    // 0..28 (col float4)
    const int br0 = tid >> 5;          // 0..7  (rows, 4 passes of 8)
    const int bc  = (tid & 31) << 2;   // 0..124

    float acc[2][8][4];
    #pragma unroll
    for (int i = 0; i < 2; i++)
        #pragma unroll
        for (int j = 0; j < 8; j++)
            #pragma unroll
            for (int t = 0; t < 4; t++) acc[i][j][t] = 0.0f;

    for (int k0 = 0; k0 < K; k0 += BK) {
        // stage A tile (convert fp32 -> bf16 hi/lo)
        #pragma unroll
        for (int p = 0; p < 4; p++) {
            int r = ar0 + p * 32;
            float4 v = make_float4(0.f, 0.f, 0.f, 0.f);
            if (bm + r < M) v = *(const float4*)(A + (size_t)(bm + r) * K + k0 + ac);
            __nv_bfloat16 h, l;
            split2(v.x, h, l); Ahi[r][ac + 0] = h; Alo[r][ac + 0] = l;
            split2(v.y, h, l); Ahi[r][ac + 1] = h; Alo[r][ac + 1] = l;
            split2(v.z, h, l); Ahi[r][ac + 2] = h; Alo[r][ac + 2] = l;
            split2(v.w, h, l); Ahi[r][ac + 3] = h; Alo[r][ac + 3] = l;
        }
        // stage B tile
        #pragma unroll
        for (int p = 0; p < 4; p++) {
            int r = br0 + p * 8;
            float4 v = *(const float4*)(B + (size_t)(k0 + r) * N + bn + bc);
            __nv_bfloat16 h, l;
            split2(v.x, h, l); Bhi[r][bc + 0] = h; Blo[r][bc + 0] = l;
            split2(v.y, h, l); Bhi[r][bc + 1] = h; Blo[r][bc + 1] = l;
            split2(v.z, h, l); Bhi[r][bc + 2] = h; Blo[r][bc + 2] = l;
            split2(v.w, h, l); Bhi[r][bc + 3] = h; Blo[r][bc + 3] = l;
        }
        __syncthreads();

        #pragma unroll
        for (int ks = 0; ks < 2; ks++) {
            uint32_t ahi[2][4], alo[2][4], bhi[8][2], blo[8][2];
            #pragma unroll
            for (int mt = 0; mt < 2; mt++) {
                const int rr = wm * 32 + mt * 16 + (lane & 15);
                const int cc = ks * 16 + ((lane >> 4) << 3);
                ldsm_x4(ahi[mt], &Ahi[rr][cc]);
                ldsm_x4(alo[mt], &Alo[rr][cc]);
            }
            #pragma unroll
            for (int nt = 0; nt < 4; nt++) {
                const int rr = ks * 16 + (lane & 15);
                const int cc = wn * 64 + nt * 16 + ((lane >> 4) << 3);
                uint32_t th[4], tl[4];
                ldsm_x4t(th, &Bhi[rr][cc]);
                ldsm_x4t(tl, &Blo[rr][cc]);
                bhi[nt * 2][0] = th[0]; bhi[nt * 2][1] = th[1];
                bhi[nt * 2 + 1][0] = th[2]; bhi[nt * 2 + 1][1] = th[3];
                blo[nt * 2][0] = tl[0]; blo[nt * 2][1] = tl[1];
                blo[nt * 2 + 1][0] = tl[2]; blo[nt * 2 + 1][1] = tl[3];
            }
            #pragma unroll
            for (int mt = 0; mt < 2; mt++)
                #pragma unroll
                for (int nb = 0; nb < 8; nb++) {
                    mma_bf16(acc[mt][nb], ahi[mt], bhi[nb]);
                    mma_bf16(acc[mt][nb], ahi[mt], blo[nb]);
                    mma_bf16(acc[mt][nb], alo[mt], bhi[nb]);
                }
        }
        __syncthreads();
    }

    // epilogue
    const int g = lane >> 2;
    const int t4 = lane & 3;
    #pragma unroll
    for (int mt = 0; mt < 2; mt++) {
        #pragma unroll
        for (int nb = 0; nb < 8; nb++) {
            int col = bn + wn * 64 + nb * 8 + t4 * 2;
            float b0 = bias[col], b1 = bias[col + 1];
            #pragma unroll
            for (int half = 0; half < 2; half++) {
                int row = bm + wm * 32 + mt * 16 + g + half * 8;
                if (row >= M) continue;
                float v0 = acc[mt][nb][half * 2 + 0] + b0;
                float v1 = acc[mt][nb][half * 2 + 1] + b1;
                float* cp = C + (size_t)row * N + col;
                if (mode == 1) {
                    float2 old = *(const float2*)cp;
                    v0 += old.x; v1 += old.y;
                } else if (mode == 2) {
                    v0 = 0.5f * v0 * (1.0f + erff(v0 * 0.70710678118654752440f));
                    v1 = 0.5f * v1 * (1.0f + erff(v1 * 0.70710678118654752440f));
                } else if (mode == 3) {
                    float2 rr = *(const float2*)(R + (size_t)row * N + col);
                    v0 += rr.x; v1 += rr.y;
                }
                *(float2*)cp = make_float2(v0, v1);
            }
        }
    }
}

// ---------------------------------------------------------------------------
// Edge pass A: exp(score) + segment sum (q,k from packed qkv, row stride 384)
// ---------------------------------------------------------------------------
__global__ void k_edge_score(const float* __restrict__ qkv,
                             float* __restrict__ escore, float* __restrict__ ssum,
                             EdgeCtx ec)
{
    int e = (blockIdx.x * blockDim.x + threadIdx.x) >> 5;
    int lane = threadIdx.x & 31;
    if (e >= ec.E) return;
    int s, d; get_edge(ec, e, s, d);
    float4 qa = *(const float4*)(qkv + (size_t)d * QKVN + lane * 4);          // q block
    float4 ka = *(const float4*)(qkv + (size_t)s * QKVN + 128 + lane * 4);    // k block
    float dp = qa.x * ka.x + qa.y * ka.y + qa.z * ka.z + qa.w * ka.w;
    dp += __shfl_xor_sync(0xffffffffu, dp, 1);
    dp += __shfl_xor_sync(0xffffffffu, dp, 2);
    if ((lane & 3) == 0) {
        int h = lane >> 2;
        float ex = __expf(dp * 0.25f);  // 1/sqrt(16)
        escore[(size_t)e * HEADS + h] = ex;
        atomicAdd(&ssum[(size_t)d * HEADS + h], ex);
    }
}

// ---------------------------------------------------------------------------
// Edge pass C: agg[dst] += alpha * v[src]
// ---------------------------------------------------------------------------
__device__ __forceinline__ void red_add_v4(float* p, float x, float y, float z, float w) {
    asm volatile("red.global.add.v4.f32 [%0], {%1, %2, %3, %4};"
                 :: "l"(p), "f"(x), "f"(y), "f"(z), "f"(w) : "memory");
}

__global__ void k_edge_agg(const float* __restrict__ qkv, const float* __restrict__ escore,
                           const float* __restrict__ ssum, float* __restrict__ agg,
                           EdgeCtx ec)
{
    int e = (blockIdx.x * blockDim.x + threadIdx.x) >> 5;
    int lane = threadIdx.x & 31;
    if (e >= ec.E) return;
    int s, d; get_edge(ec, e, s, d);
    int h = lane >> 2;
    float alpha = escore[(size_t)e * HEADS + h] / (ssum[(size_t)d * HEADS + h] + 1e-16f);
    float4 va = *(const float4*)(qkv + (size_t)s * QKVN + 256 + lane * 4);    // v block
    red_add_v4(agg + (size_t)d * HIDDEN + lane * 4,
               alpha * va.x, alpha * va.y, alpha * va.z, alpha * va.w);
}

// ---------------------------------------------------------------------------
// LayerNorm: one warp per row of 128
// ---------------------------------------------------------------------------
__global__ void k_layernorm(const float* __restrict__ in, const float* __restrict__ g,
                            const float* __restrict__ b, float* __restrict__ out, int M)
{
    int row = blockIdx.x * (blockDim.x >> 5) + (threadIdx.x >> 5);
    int lane = threadIdx.x & 31;
    if (row >= M) return;
    const float* p = in + (size_t)row * HIDDEN;
    float vals[4], s = 0.0f, s2 = 0.0f;
    #pragma unroll
    for (int i = 0; i < 4; i++) {
        float v = p[lane + i * 32];
        vals[i] = v; s += v; s2 += v * v;
    }
    #pragma unroll
    for (int o = 16; o; o >>= 1) {
        s  += __shfl_xor_sync(0xffffffffu, s,  o);
        s2 += __shfl_xor_sync(0xffffffffu, s2, o);
    }
    float mu  = s * (1.0f / HIDDEN);
    float var = s2 * (1.0f / HIDDEN) - mu * mu;
    float inv = rsqrtf(var + 1e-5f);
    #pragma unroll
    for (int i = 0; i < 4; i++) {
        int c = lane + i * 32;
        out[(size_t)row * HIDDEN + c] = (vals[i] - mu) * inv * g[c] + b[c];
    }
}

// ---------------------------------------------------------------------------
// Host-side orchestration
// ---------------------------------------------------------------------------
static inline dim3 grid1(size_t n, int bs) { return dim3((unsigned)((n + bs - 1) / bs)); }

static void launch_gemm(const float* A, const float* B, const float* bias, float* C,
                        const float* R, int M, int N, int K, int mode) {
    dim3 g(N / BN, (M + BM - 1) / BM);
    k_hgemm<<<g, 256>>>(A, B, bias, C, R, M, N, K, mode);
}

static void run_attention(const float* xv, float* acc,
                          float* qkv, float* agg, float* sc, float* ssum,
                          float* wqkv, float* bqkv,
                          const float* wq, const float* bq,
                          const float* wk, const float* bk,
                          const float* wv, const float* bv,
                          const float* wo, const float* bo,
                          EdgeCtx ec, int omode)
{
    k_pack_qkv<<<grid1(HIDDEN * QKVN, 256), 256>>>(wq, wk, wv, bq, bk, bv, wqkv, bqkv);
    launch_gemm(xv, wqkv, bqkv, qkv, nullptr, NV, QKVN, HIDDEN, 0);

    k_zero<<<grid1((size_t)NV * HEADS, 256), 256>>>(ssum, (size_t)NV * HEADS);
    k_zero<<<grid1((size_t)NV * HIDDEN, 256), 256>>>(agg, (size_t)NV * HIDDEN);

    size_t thr = (size_t)ec.E * 32;
    k_edge_score<<<grid1(thr, 256), 256>>>(qkv, sc, ssum, ec);
    k_edge_agg  <<<grid1(thr, 256), 256>>>(qkv, sc, ssum, agg, ec);

    launch_gemm(agg, wo, bo, acc, xv, NV, HIDDEN, HIDDEN, omode);
}

extern "C" void kernel_launch(void* const* d_in, const int* in_sizes, int n_in,
                              void* d_out, int out_size)
{
    (void)n_in; (void)in_sizes; (void)out_size;
    const float* x         = (const float*)d_in[0];
    const int*   edge_idx  = (const int*)  d_in[1];
    const int*   exp_edges = (const int*)  d_in[2];
    const float* lq_w = (const float*)d_in[3];   const float* lq_b = (const float*)d_in[4];
    const float* lk_w = (const float*)d_in[5];   const float* lk_b = (const float*)d_in[6];
    const float* lv_w = (const float*)d_in[7];   const float* lv_b = (const float*)d_in[8];
    const float* lo_w = (const float*)d_in[9];   const float* lo_b = (const float*)d_in[10];
    const float* eq_w = (const float*)d_in[11];  const float* eq_b = (const float*)d_in[12];
    const float* ek_w = (const float*)d_in[13];  const float* ek_b = (const float*)d_in[14];
    const float* ev_w = (const float*)d_in[15];  const float* ev_b = (const float*)d_in[16];
    const float* eo_w = (const float*)d_in[17];  const float* eo_b = (const float*)d_in[18];
    const float* ln_g = (const float*)d_in[19];  const float* ln_b = (const float*)d_in[20];
    const float* ffn_w1 = (const float*)d_in[21]; const float* ffn_b1 = (const float*)d_in[22];
    const float* ffn_w2 = (const float*)d_in[23]; const float* ffn_b2 = (const float*)d_in[24];

    float *xv, *acc, *qkv, *agg, *h1, *sc, *ssum, *wqkv, *bqkv;
    cudaGetSymbolAddress((void**)&xv,   g_xv);
    cudaGetSymbolAddress((void**)&acc,  g_acc);
    cudaGetSymbolAddress((void**)&qkv,  g_qkv);
    cudaGetSymbolAddress((void**)&agg,  g_agg);
    cudaGetSymbolAddress((void**)&h1,   g_h1);
    cudaGetSymbolAddress((void**)&sc,   g_sc);
    cudaGetSymbolAddress((void**)&ssum, g_s);
    cudaGetSymbolAddress((void**)&wqkv, g_wqkv);
    cudaGetSymbolAddress((void**)&bqkv, g_bqkv);

    const size_t nvh = (size_t)NV * HIDDEN;

    k_build_xv<<<grid1(nvh / 4, 256), 256>>>((const float4*)x, (float4*)xv);

    for (int l = 0; l < LAYERS; l++) {
        EdgeCtx ec_local;
        ec_local.a = edge_idx; ec_local.b = edge_idx + N_EDGES;
        ec_local.E0 = N_EDGES; ec_local.n = N_NODES;
        ec_local.E = E_LOCAL;  ec_local.mode = 0;
        run_attention(xv, acc, qkv, agg, sc, ssum, wqkv, bqkv,
                      lq_w + (size_t)l * HIDDEN * HIDDEN, lq_b + (size_t)l * HIDDEN,
                      lk_w + (size_t)l * HIDDEN * HIDDEN, lk_b + (size_t)l * HIDDEN,
                      lv_w + (size_t)l * HIDDEN * HIDDEN, lv_b + (size_t)l * HIDDEN,
                      lo_w + (size_t)l * HIDDEN * HIDDEN, lo_b + (size_t)l * HIDDEN,
                      ec_local, /*omode=*/3);

        EdgeCtx ec_exp;
        ec_exp.a = exp_edges + (size_t)l * 2 * E_EXP;
        ec_exp.b = ec_exp.a + E_EXP;
        ec_exp.E0 = 0; ec_exp.n = N_NODES;
        ec_exp.E = E_EXP; ec_exp.mode = 1;
        run_attention(xv, acc, qkv, agg, sc, ssum, wqkv, bqkv,
                      eq_w + (size_t)l * HIDDEN * HIDDEN, eq_b + (size_t)l * HIDDEN,
                      ek_w + (size_t)l * HIDDEN * HIDDEN, ek_b + (size_t)l * HIDDEN,
                      ev_w + (size_t)l * HIDDEN * HIDDEN, ev_b + (size_t)l * HIDDEN,
                      eo_w + (size_t)l * HIDDEN * HIDDEN, eo_b + (size_t)l * HIDDEN,
                      ec_exp, /*omode=*/1);

        {
            int wpb = 8;
            dim3 g((NV + wpb - 1) / wpb);
            k_layernorm<<<g, wpb * 32>>>(acc, ln_g + (size_t)l * HIDDEN,
                                         ln_b + (size_t)l * HIDDEN, xv, NV);
        }

        launch_gemm(xv, ffn_w1 + (size_t)l * HIDDEN * 4 * HIDDEN,
                    ffn_b1 + (size_t)l * 4 * HIDDEN, h1, nullptr,
                    NV, 4 * HIDDEN, HIDDEN, 2);
        launch_gemm(h1, ffn_w2 + (size_t)l * 4 * HIDDEN * HIDDEN,
                    ffn_b2 + (size_t)l * HIDDEN, xv, nullptr,
                    NV, HIDDEN, 4 * HIDDEN, 1);
    }

    k_copy4<<<grid1((size_t)N_NODES * HIDDEN / 4, 256), 256>>>(
        (float4*)d_out, (const float4*)xv, (size_t)N_NODES * HIDDEN / 4);
}

// round 4
// speedup vs baseline: 3.2407x; 1.3598x over previous
#include <cuda_runtime.h>
#include <cuda_bf16.h>
#include <math.h>
#include <stdint.h>

// ---------------------------------------------------------------------------
// Problem constants
// ---------------------------------------------------------------------------
#define N_NODES 20000
#define N_EDGES 320000
#define HIDDEN  128
#define HEADS   8
#define LAYERS  3
#define NV      (N_NODES + 1)
#define E_EXP   (NV * 4)                 // 80004
#define QKVN    (3 * HIDDEN)             // 384

// ---------------------------------------------------------------------------
// Scratch (device globals; no allocations)
// ---------------------------------------------------------------------------
__device__ float g_xv   [(size_t)NV * HIDDEN];
__device__ float g_acc  [(size_t)NV * HIDDEN];
__device__ float g_qkv  [(size_t)NV * QKVN];
__device__ float g_agg  [(size_t)NV * HIDDEN];
__device__ float g_h1   [(size_t)NV * 4 * HIDDEN];
__device__ float g_wqkv [(size_t)HIDDEN * QKVN];
__device__ float g_bqkv [QKVN];
// CSR scratch
__device__ int   g_cnt    [NV];
__device__ int   g_rowptrL[NV + 1];   // local graph (built once per call)
__device__ int   g_esrcL  [N_EDGES];
__device__ int   g_rowptrE[NV + 1];   // expander (rebuilt per layer)
__device__ int   g_esrcE  [E_EXP];
__device__ int   g_cursor [NV];
// virtual-node reduction scratch
__device__ float g_vnacc[HIDDEN];
__device__ float g_vnsum[HEADS];

// ---------------------------------------------------------------------------
// Utility kernels
// ---------------------------------------------------------------------------
__global__ void k_copy4(float4* __restrict__ dst, const float4* __restrict__ src, size_t n4) {
    size_t i = (size_t)blockIdx.x * blockDim.x + threadIdx.x;
    if (i < n4) dst[i] = src[i];
}
__global__ void k_zero_i(int* p, int n) {
    int i = blockIdx.x * blockDim.x + threadIdx.x;
    if (i < n) p[i] = 0;
}
__global__ void k_copy_i(int* __restrict__ dst, const int* __restrict__ src, int n) {
    int i = blockIdx.x * blockDim.x + threadIdx.x;
    if (i < n) dst[i] = src[i];
}
__global__ void k_zero_vn(float* vnacc, float* vnsum) {
    int i = threadIdx.x;
    if (i < HIDDEN) vnacc[i] = 0.0f;
    if (i < HEADS)  vnsum[i] = 0.0f;
}
__global__ void k_build_xv(const float4* __restrict__ x, float4* __restrict__ xv) {
    size_t i = (size_t)blockIdx.x * blockDim.x + threadIdx.x;
    size_t tot = (size_t)NV * HIDDEN / 4;
    size_t lim = (size_t)N_NODES * HIDDEN / 4;
    if (i < tot) xv[i] = (i < lim) ? x[i] : make_float4(0.f, 0.f, 0.f, 0.f);
}
__global__ void k_pack_qkv(const float* __restrict__ wq, const float* __restrict__ wk,
                           const float* __restrict__ wv, const float* __restrict__ bq,
                           const float* __restrict__ bk, const float* __restrict__ bv,
                           float* __restrict__ wout, float* __restrict__ bout) {
    int i = blockIdx.x * blockDim.x + threadIdx.x;
    if (i < HIDDEN * QKVN) {
        int k = i / QKVN, n = i % QKVN;
        const float* src = (n < 128) ? wq : (n < 256 ? wk : wv);
        wout[i] = src[k * HIDDEN + (n & 127)];
    }
    if (i < QKVN) {
        const float* bs = (i < 128) ? bq : (i < 256 ? bk : bv);
        bout[i] = bs[i & 127];
    }
}

// ---------------------------------------------------------------------------
// CSR build: histogram -> exclusive scan -> scatter (store src per slot)
// ---------------------------------------------------------------------------
__global__ void k_hist(const int* __restrict__ dst, int E, int* __restrict__ cnt) {
    int e = blockIdx.x * blockDim.x + threadIdx.x;
    if (e < E) atomicAdd(&cnt[dst[e]], 1);
}
__global__ void k_scan(const int* __restrict__ cnt, int* __restrict__ rowptr, int n) {
    __shared__ int sh[1024];
    __shared__ int carry;
    if (threadIdx.x == 0) carry = 0;
    __syncthreads();
    for (int base = 0; base < n; base += 1024) {
        int i = base + (int)threadIdx.x;
        int v = (i < n) ? cnt[i] : 0;
        sh[threadIdx.x] = v;
        __syncthreads();
        #pragma unroll
        for (int off = 1; off < 1024; off <<= 1) {
            int t = (threadIdx.x >= (unsigned)off) ? sh[threadIdx.x - off] : 0;
            __syncthreads();
            sh[threadIdx.x] += t;
            __syncthreads();
        }
        if (i < n) rowptr[i + 1] = sh[threadIdx.x] + carry;
        __syncthreads();
        if (threadIdx.x == 0) carry += sh[1023];
        __syncthreads();
    }
    if (threadIdx.x == 0) rowptr[0] = 0;
}
__global__ void k_scatter(const int* __restrict__ src, const int* __restrict__ dst,
                          int E, int* __restrict__ cursor, int* __restrict__ esrc) {
    int e = blockIdx.x * blockDim.x + threadIdx.x;
    if (e < E) {
        int pos = atomicAdd(&cursor[dst[e]], 1);
        esrc[pos] = src[e];
    }
}

// ---------------------------------------------------------------------------
// Tensor-core GEMM (bf16 hi/lo split, fp32 accumulate) — same as R3
// ---------------------------------------------------------------------------
#define BM 128
#define BN 128
#define BK 32
#define APAD 8
#define BPAD 8

__device__ __forceinline__ void ldsm_x4(uint32_t* r, const void* p) {
    uint32_t a = (uint32_t)__cvta_generic_to_shared(p);
    asm volatile("ldmatrix.sync.aligned.m8n8.x4.shared.b16 {%0,%1,%2,%3}, [%4];"
                 : "=r"(r[0]), "=r"(r[1]), "=r"(r[2]), "=r"(r[3]) : "r"(a));
}
__device__ __forceinline__ void ldsm_x4t(uint32_t* r, const void* p) {
    uint32_t a = (uint32_t)__cvta_generic_to_shared(p);
    asm volatile("ldmatrix.sync.aligned.m8n8.x4.trans.shared.b16 {%0,%1,%2,%3}, [%4];"
                 : "=r"(r[0]), "=r"(r[1]), "=r"(r[2]), "=r"(r[3]) : "r"(a));
}
__device__ __forceinline__ void mma_bf16(float* c, const uint32_t* a, const uint32_t* b) {
    asm volatile("mma.sync.aligned.m16n8k16.row.col.f32.bf16.bf16.f32 "
                 "{%0,%1,%2,%3}, {%4,%5,%6,%7}, {%8,%9}, {%0,%1,%2,%3};"
                 : "+f"(c[0]), "+f"(c[1]), "+f"(c[2]), "+f"(c[3])
                 : "r"(a[0]), "r"(a[1]), "r"(a[2]), "r"(a[3]), "r"(b[0]), "r"(b[1]));
}
__device__ __forceinline__ void split2(float x, __nv_bfloat16& h, __nv_bfloat16& l) {
    h = __float2bfloat16_rn(x);
    l = __float2bfloat16_rn(x - __bfloat162float(h));
}

__global__ __launch_bounds__(256) void k_hgemm(
    const float* __restrict__ A, const float* __restrict__ B,
    const float* __restrict__ bias, float* __restrict__ C,
    const float* __restrict__ R,
    int M, int N, int K, int mode)
{
    __shared__ __align__(16) __nv_bfloat16 Ahi[BM][BK + APAD];
    __shared__ __align__(16) __nv_bfloat16 Alo[BM][BK + APAD];
    __shared__ __align__(16) __nv_bfloat16 Bhi[BK][BN + BPAD];
    __shared__ __align__(16) __nv_bfloat16 Blo[BK][BN + BPAD];

    const int bm = blockIdx.y * BM;
    const int bn = blockIdx.x * BN;
    const int tid = threadIdx.x;
    const int lane = tid & 31;
    const int w = tid >> 5;
    const int wm = w & 3;
    const int wn = w >> 2;

    const int ar0 = tid >> 3;
    const int ac  = (tid & 7) << 2;
    const int br0 = tid >> 5;
    const int bc  = (tid & 31) << 2;

    float acc[2][8][4];
    #pragma unroll
    for (int i = 0; i < 2; i++)
        #pragma unroll
        for (int j = 0; j < 8; j++)
            #pragma unroll
            for (int t = 0; t < 4; t++) acc[i][j][t] = 0.0f;

    for (int k0 = 0; k0 < K; k0 += BK) {
        #pragma unroll
        for (int p = 0; p < 4; p++) {
            int r = ar0 + p * 32;
            float4 v = make_float4(0.f, 0.f, 0.f, 0.f);
            if (bm + r < M) v = *(const float4*)(A + (size_t)(bm + r) * K + k0 + ac);
            __nv_bfloat16 h, l;
            split2(v.x, h, l); Ahi[r][ac + 0] = h; Alo[r][ac + 0] = l;
            split2(v.y, h, l); Ahi[r][ac + 1] = h; Alo[r][ac + 1] = l;
            split2(v.z, h, l); Ahi[r][ac + 2] = h; Alo[r][ac + 2] = l;
            split2(v.w, h, l); Ahi[r][ac + 3] = h; Alo[r][ac + 3] = l;
        }
        #pragma unroll
        for (int p = 0; p < 4; p++) {
            int r = br0 + p * 8;
            float4 v = *(const float4*)(B + (size_t)(k0 + r) * N + bn + bc);
            __nv_bfloat16 h, l;
            split2(v.x, h, l); Bhi[r][bc + 0] = h; Blo[r][bc + 0] = l;
            split2(v.y, h, l); Bhi[r][bc + 1] = h; Blo[r][bc + 1] = l;
            split2(v.z, h, l); Bhi[r][bc + 2] = h; Blo[r][bc + 2] = l;
            split2(v.w, h, l); Bhi[r][bc + 3] = h; Blo[r][bc + 3] = l;
        }
        __syncthreads();

        #pragma unroll
        for (int ks = 0; ks < 2; ks++) {
            uint32_t ahi[2][4], alo[2][4], bhi[8][2], blo[8][2];
            #pragma unroll
            for (int mt = 0; mt < 2; mt++) {
                const int rr = wm * 32 + mt * 16 + (lane & 15);
                const int cc = ks * 16 + ((lane >> 4) << 3);
                ldsm_x4(ahi[mt], &Ahi[rr][cc]);
                ldsm_x4(alo[mt], &Alo[rr][cc]);
            }
            #pragma unroll
            for (int nt = 0; nt < 4; nt++) {
                const int rr = ks * 16 + (lane & 15);
                const int cc = wn * 64 + nt * 16 + ((lane >> 4) << 3);
                uint32_t th[4], tl[4];
                ldsm_x4t(th, &Bhi[rr][cc]);
                ldsm_x4t(tl, &Blo[rr][cc]);
                bhi[nt * 2][0] = th[0]; bhi[nt * 2][1] = th[1];
                bhi[nt * 2 + 1][0] = th[2]; bhi[nt * 2 + 1][1] = th[3];
                blo[nt * 2][0] = tl[0]; blo[nt * 2][1] = tl[1];
                blo[nt * 2 + 1][0] = tl[2]; blo[nt * 2 + 1][1] = tl[3];
            }
            #pragma unroll
            for (int mt = 0; mt < 2; mt++)
                #pragma unroll
                for (int nb = 0; nb < 8; nb++) {
                    mma_bf16(acc[mt][nb], ahi[mt], bhi[nb]);
                    mma_bf16(acc[mt][nb], ahi[mt], blo[nb]);
                    mma_bf16(acc[mt][nb], alo[mt], bhi[nb]);
                }
        }
        __syncthreads();
    }

    const int g = lane >> 2;
    const int t4 = lane & 3;
    #pragma unroll
    for (int mt = 0; mt < 2; mt++) {
        #pragma unroll
        for (int nb = 0; nb < 8; nb++) {
            int col = bn + wn * 64 + nb * 8 + t4 * 2;
            float b0 = bias[col], b1 = bias[col + 1];
            #pragma unroll
            for (int half = 0; half < 2; half++) {
                int row = bm + wm * 32 + mt * 16 + g + half * 8;
                if (row >= M) continue;
                float v0 = acc[mt][nb][half * 2 + 0] + b0;
                float v1 = acc[mt][nb][half * 2 + 1] + b1;
                float* cp = C + (size_t)row * N + col;
                if (mode == 1) {
                    float2 old = *(const float2*)cp;
                    v0 += old.x; v1 += old.y;
                } else if (mode == 2) {
                    v0 = 0.5f * v0 * (1.0f + erff(v0 * 0.70710678118654752440f));
                    v1 = 0.5f * v1 * (1.0f + erff(v1 * 0.70710678118654752440f));
                } else if (mode == 3) {
                    float2 rr = *(const float2*)(R + (size_t)row * N + col);
                    v0 += rr.x; v1 += rr.y;
                }
                *(float2*)cp = make_float2(v0, v1);
            }
        }
    }
}

// ---------------------------------------------------------------------------
// Fused gather attention: one warp per destination node.
//   out[d] = sum_e exp(q[d]·k[src_e]/4) * v[src_e]  /  sum_e exp(...)
// Lane l holds dims [4l, 4l+4); head = l>>2; per-head dot via 2 shuffles.
// addVN: append one implicit edge with src = vnid (local mode).
// ---------------------------------------------------------------------------
__global__ void k_gather(const float* __restrict__ qkv, float* __restrict__ agg,
                         const int* __restrict__ rowptr, const int* __restrict__ esrc,
                         int nDst, int addVN, int vnid)
{
    int d = (blockIdx.x * blockDim.x + threadIdx.x) >> 5;
    int lane = threadIdx.x & 31;
    if (d >= nDst) return;

    float4 qd = *(const float4*)(qkv + (size_t)d * QKVN + lane * 4);
    float4 vacc = make_float4(0.f, 0.f, 0.f, 0.f);
    float ssum = 0.0f;

    int beg = rowptr[d];
    int end = rowptr[d + 1];
    for (int e = beg; e <= end; e++) {          // one extra trip for implicit vn edge
        int s;
        if (e < end) s = esrc[e];
        else if (addVN) s = vnid;
        else break;
        const float* row = qkv + (size_t)s * QKVN;
        float4 ka = *(const float4*)(row + 128 + lane * 4);
        float dp = qd.x * ka.x + qd.y * ka.y + qd.z * ka.z + qd.w * ka.w;
        dp += __shfl_xor_sync(0xffffffffu, dp, 1);
        dp += __shfl_xor_sync(0xffffffffu, dp, 2);
        float ex = __expf(dp * 0.25f);
        float4 va = *(const float4*)(row + 256 + lane * 4);
        vacc.x = fmaf(ex, va.x, vacc.x);
        vacc.y = fmaf(ex, va.y, vacc.y);
        vacc.z = fmaf(ex, va.z, vacc.z);
        vacc.w = fmaf(ex, va.w, vacc.w);
        ssum += ex;
    }
    float inv = 1.0f / (ssum + 1e-16f);
    *(float4*)(agg + (size_t)d * HIDDEN + lane * 4) =
        make_float4(vacc.x * inv, vacc.y * inv, vacc.z * inv, vacc.w * inv);
}

// ---------------------------------------------------------------------------
// Virtual-node destination (local graph): in-edges are exactly src=0..n-1.
// Grid-stride warps accumulate partials, then atomically reduce.
// ---------------------------------------------------------------------------
__device__ __forceinline__ void red_add_v4(float* p, float x, float y, float z, float w) {
    asm volatile("red.global.add.v4.f32 [%0], {%1, %2, %3, %4};"
                 :: "l"(p), "f"(x), "f"(y), "f"(z), "f"(w) : "memory");
}

__global__ void k_vn_partial(const float* __restrict__ qkv,
                             float* __restrict__ vnacc, float* __restrict__ vnsum,
                             int vnid)
{
    int warp = (blockIdx.x * blockDim.x + threadIdx.x) >> 5;
    int lane = threadIdx.x & 31;
    int nwarps = (gridDim.x * blockDim.x) >> 5;

    float4 qd = *(const float4*)(qkv + (size_t)vnid * QKVN + lane * 4);
    float4 vacc = make_float4(0.f, 0.f, 0.f, 0.f);
    float ssum = 0.0f;

    for (int s = warp; s < N_NODES; s += nwarps) {
        const float* row = qkv + (size_t)s * QKVN;
        float4 ka = *(const float4*)(row + 128 + lane * 4);
        float dp = qd.x * ka.x + qd.y * ka.y + qd.z * ka.z + qd.w * ka.w;
        dp += __shfl_xor_sync(0xffffffffu, dp, 1);
        dp += __shfl_xor_sync(0xffffffffu, dp, 2);
        float ex = __expf(dp * 0.25f);
        float4 va = *(const float4*)(row + 256 + lane * 4);
        vacc.x = fmaf(ex, va.x, vacc.x);
        vacc.y = fmaf(ex, va.y, vacc.y);
        vacc.z = fmaf(ex, va.z, vacc.z);
        vacc.w = fmaf(ex, va.w, vacc.w);
        ssum += ex;
    }
    red_add_v4(vnacc + lane * 4, vacc.x, vacc.y, vacc.z, vacc.w);
    if ((lane & 3) == 0) atomicAdd(&vnsum[lane >> 2], ssum);
}

__global__ void k_vn_final(const float* __restrict__ vnacc, const float* __restrict__ vnsum,
                           float* __restrict__ agg, int vnid)
{
    int lane = threadIdx.x & 31;
    if (threadIdx.x >= 32) return;
    float inv = 1.0f / (vnsum[lane >> 2] + 1e-16f);
    float4 v = *(const float4*)(vnacc + lane * 4);
    *(float4*)(agg + (size_t)vnid * HIDDEN + lane * 4) =
        make_float4(v.x * inv, v.y * inv, v.z * inv, v.w * inv);
}

// ---------------------------------------------------------------------------
// LayerNorm: one warp per row of 128
// ---------------------------------------------------------------------------
__global__ void k_layernorm(const float* __restrict__ in, const float* __restrict__ g,
                            const float* __restrict__ b, float* __restrict__ out, int M)
{
    int row = blockIdx.x * (blockDim.x >> 5) + (threadIdx.x >> 5);
    int lane = threadIdx.x & 31;
    if (row >= M) return;
    const float* p = in + (size_t)row * HIDDEN;
    float vals[4], s = 0.0f, s2 = 0.0f;
    #pragma unroll
    for (int i = 0; i < 4; i++) {
        float v = p[lane + i * 32];
        vals[i] = v; s += v; s2 += v * v;
    }
    #pragma unroll
    for (int o = 16; o; o >>= 1) {
        s  += __shfl_xor_sync(0xffffffffu, s,  o);
        s2 += __shfl_xor_sync(0xffffffffu, s2, o);
    }
    float mu  = s * (1.0f / HIDDEN);
    float var = s2 * (1.0f / HIDDEN) - mu * mu;
    float inv = rsqrtf(var + 1e-5f);
    #pragma unroll
    for (int i = 0; i < 4; i++) {
        int c = lane + i * 32;
        out[(size_t)row * HIDDEN + c] = (vals[i] - mu) * inv * g[c] + b[c];
    }
}

// ---------------------------------------------------------------------------
// Host-side orchestration
// ---------------------------------------------------------------------------
static inline dim3 grid1(size_t n, int bs) { return dim3((unsigned)((n + bs - 1) / bs)); }

static void launch_gemm(const float* A, const float* B, const float* bias, float* C,
                        const float* R, int M, int N, int K, int mode) {
    dim3 g(N / BN, (M + BM - 1) / BM);
    k_hgemm<<<g, 256>>>(A, B, bias, C, R, M, N, K, mode);
}

static void build_csr(const int* src, const int* dst, int E,
                      int* cnt, int* rowptr, int* cursor, int* esrc) {
    k_zero_i<<<grid1(NV, 256), 256>>>(cnt, NV);
    k_hist<<<grid1(E, 256), 256>>>(dst, E, cnt);
    k_scan<<<1, 1024>>>(cnt, rowptr, NV);
    k_copy_i<<<grid1(NV, 256), 256>>>(cursor, rowptr, NV);
    k_scatter<<<grid1(E, 256), 256>>>(src, dst, E, cursor, esrc);
}

extern "C" void kernel_launch(void* const* d_in, const int* in_sizes, int n_in,
                              void* d_out, int out_size)
{
    (void)n_in; (void)in_sizes; (void)out_size;
    const float* x         = (const float*)d_in[0];
    const int*   edge_idx  = (const int*)  d_in[1];
    const int*   exp_edges = (const int*)  d_in[2];
    const float* lq_w = (const float*)d_in[3];   const float* lq_b = (const float*)d_in[4];
    const float* lk_w = (const float*)d_in[5];   const float* lk_b = (const float*)d_in[6];
    const float* lv_w = (const float*)d_in[7];   const float* lv_b = (const float*)d_in[8];
    const float* lo_w = (const float*)d_in[9];   const float* lo_b = (const float*)d_in[10];
    const float* eq_w = (const float*)d_in[11];  const float* eq_b = (const float*)d_in[12];
    const float* ek_w = (const float*)d_in[13];  const float* ek_b = (const float*)d_in[14];
    const float* ev_w = (const float*)d_in[15];  const float* ev_b = (const float*)d_in[16];
    const float* eo_w = (const float*)d_in[17];  const float* eo_b = (const float*)d_in[18];
    const float* ln_g = (const float*)d_in[19];  const float* ln_b = (const float*)d_in[20];
    const float* ffn_w1 = (const float*)d_in[21]; const float* ffn_b1 = (const float*)d_in[22];
    const float* ffn_w2 = (const float*)d_in[23]; const float* ffn_b2 = (const float*)d_in[24];

    float *xv, *acc, *qkv, *agg, *h1, *wqkv, *bqkv, *vnacc, *vnsum;
    int *cnt, *rowptrL, *esrcL, *rowptrE, *esrcE, *cursor;
    cudaGetSymbolAddress((void**)&xv,     g_xv);
    cudaGetSymbolAddress((void**)&acc,    g_acc);
    cudaGetSymbolAddress((void**)&qkv,    g_qkv);
    cudaGetSymbolAddress((void**)&agg,    g_agg);
    cudaGetSymbolAddress((void**)&h1,     g_h1);
    cudaGetSymbolAddress((void**)&wqkv,   g_wqkv);
    cudaGetSymbolAddress((void**)&bqkv,   g_bqkv);
    cudaGetSymbolAddress((void**)&vnacc,  g_vnacc);
    cudaGetSymbolAddress((void**)&vnsum,  g_vnsum);
    cudaGetSymbolAddress((void**)&cnt,    g_cnt);
    cudaGetSymbolAddress((void**)&rowptrL, g_rowptrL);
    cudaGetSymbolAddress((void**)&esrcL,  g_esrcL);
    cudaGetSymbolAddress((void**)&rowptrE, g_rowptrE);
    cudaGetSymbolAddress((void**)&esrcE,  g_esrcE);
    cudaGetSymbolAddress((void**)&cursor, g_cursor);

    const size_t nvh = (size_t)NV * HIDDEN;

    k_build_xv<<<grid1(nvh / 4, 256), 256>>>((const float4*)x, (float4*)xv);

    // Local CSR: raw edges only (dst < N_NODES always; vn edges handled implicitly)
    build_csr(edge_idx, edge_idx + N_EDGES, N_EDGES, cnt, rowptrL, cursor, esrcL);

    for (int l = 0; l < LAYERS; l++) {
        // ----- local attention: acc = xv + O(attn_local(xv)) -----
        k_pack_qkv<<<grid1(HIDDEN * QKVN, 256), 256>>>(
            lq_w + (size_t)l * HIDDEN * HIDDEN, lk_w + (size_t)l * HIDDEN * HIDDEN,
            lv_w + (size_t)l * HIDDEN * HIDDEN,
            lq_b + (size_t)l * HIDDEN, lk_b + (size_t)l * HIDDEN, lv_b + (size_t)l * HIDDEN,
            wqkv, bqkv);
        launch_gemm(xv, wqkv, bqkv, qkv, nullptr, NV, QKVN, HIDDEN, 0);

        k_gather<<<grid1((size_t)N_NODES * 32, 256), 256>>>(
            qkv, agg, rowptrL, esrcL, N_NODES, /*addVN=*/1, N_NODES);
        k_zero_vn<<<1, 128>>>(vnacc, vnsum);
        k_vn_partial<<<128, 256>>>(qkv, vnacc, vnsum, N_NODES);
        k_vn_final<<<1, 32>>>(vnacc, vnsum, agg, N_NODES);

        launch_gemm(agg, lo_w + (size_t)l * HIDDEN * HIDDEN, lo_b + (size_t)l * HIDDEN,
                    acc, xv, NV, HIDDEN, HIDDEN, /*mode=*/3);

        // ----- expander attention: acc += O(attn_exp(xv)) -----
        const int* esrc_in = exp_edges + (size_t)l * 2 * E_EXP;
        const int* edst_in = esrc_in + E_EXP;
        build_csr(esrc_in, edst_in, E_EXP, cnt, rowptrE, cursor, esrcE);

        k_pack_qkv<<<grid1(HIDDEN * QKVN, 256), 256>>>(
            eq_w + (size_t)l * HIDDEN * HIDDEN, ek_w + (size_t)l * HIDDEN * HIDDEN,
            ev_w + (size_t)l * HIDDEN * HIDDEN,
            eq_b + (size_t)l * HIDDEN, ek_b + (size_t)l * HIDDEN, ev_b + (size_t)l * HIDDEN,
            wqkv, bqkv);
        launch_gemm(xv, wqkv, bqkv, qkv, nullptr, NV, QKVN, HIDDEN, 0);

        k_gather<<<grid1((size_t)NV * 32, 256), 256>>>(
            qkv, agg, rowptrE, esrcE, NV, /*addVN=*/0, N_NODES);

        launch_gemm(agg, eo_w + (size_t)l * HIDDEN * HIDDEN, eo_b + (size_t)l * HIDDEN,
                    acc, nullptr, NV, HIDDEN, HIDDEN, /*mode=*/1);

        // ----- LN -----
        {
            int wpb = 8;
            dim3 g((NV + wpb - 1) / wpb);
            k_layernorm<<<g, wpb * 32>>>(acc, ln_g + (size_t)l * HIDDEN,
                                         ln_b + (size_t)l * HIDDEN, xv, NV);
        }

        // ----- FFN -----
        launch_gemm(xv, ffn_w1 + (size_t)l * HIDDEN * 4 * HIDDEN,
                    ffn_b1 + (size_t)l * 4 * HIDDEN, h1, nullptr,
                    NV, 4 * HIDDEN, HIDDEN, 2);
        launch_gemm(h1, ffn_w2 + (size_t)l * 4 * HIDDEN * HIDDEN,
                    ffn_b2 + (size_t)l * HIDDEN, xv, nullptr,
                    NV, HIDDEN, 4 * HIDDEN, 1);
    }

    k_copy4<<<grid1((size_t)N_NODES * HIDDEN / 4, 256), 256>>>(
        (float4*)d_out, (const float4*)xv, (size_t)N_NODES * HIDDEN / 4);
}

// round 5
// speedup vs baseline: 4.5113x; 1.3921x over previous
#include <cuda_runtime.h>
#include <cuda_bf16.h>
#include <math.h>
#include <stdint.h>

// ---------------------------------------------------------------------------
// Problem constants
// ---------------------------------------------------------------------------
#define N_NODES 20000
#define N_EDGES 320000
#define HIDDEN  128
#define HEADS   8
#define LAYERS  3
#define NV      (N_NODES + 1)
#define E_EXP   (NV * 4)                 // 80004
#define QKVN    (3 * HIDDEN)             // 384

// ---------------------------------------------------------------------------
// Scratch (device globals; no allocations)
// ---------------------------------------------------------------------------
__device__ float g_xv   [(size_t)NV * HIDDEN];
__device__ float g_acc  [(size_t)NV * HIDDEN];
__device__ float g_qkv  [(size_t)NV * QKVN];
__device__ float g_agg  [(size_t)NV * HIDDEN];
__device__ float g_h1   [(size_t)NV * 4 * HIDDEN];
__device__ float g_wqkv [(size_t)HIDDEN * QKVN];
__device__ float g_bqkv [QKVN];
// CSR scratch (local graph only; expander is implicit fixed-degree-4)
__device__ int   g_cnt    [NV];
__device__ int   g_rowptrL[NV + 1];
__device__ int   g_esrcL  [N_EDGES];
__device__ int   g_esrcE  [E_EXP];
__device__ int   g_cursor [NV];
// virtual-node reduction scratch
__device__ float g_vnacc[HIDDEN];
__device__ float g_vnsum[HEADS];

// ---------------------------------------------------------------------------
// Utility kernels
// ---------------------------------------------------------------------------
__global__ void k_copy4(float4* __restrict__ dst, const float4* __restrict__ src, size_t n4) {
    size_t i = (size_t)blockIdx.x * blockDim.x + threadIdx.x;
    if (i < n4) dst[i] = src[i];
}
__global__ void k_zero_i(int* p, int n) {
    int i = blockIdx.x * blockDim.x + threadIdx.x;
    if (i < n) p[i] = 0;
}
__global__ void k_copy_i(int* __restrict__ dst, const int* __restrict__ src, int n) {
    int i = blockIdx.x * blockDim.x + threadIdx.x;
    if (i < n) dst[i] = src[i];
}
__global__ void k_zero_vn(float* vnacc, float* vnsum) {
    int i = threadIdx.x;
    if (i < HIDDEN) vnacc[i] = 0.0f;
    if (i < HEADS)  vnsum[i] = 0.0f;
}
__global__ void k_build_xv(const float4* __restrict__ x, float4* __restrict__ xv) {
    size_t i = (size_t)blockIdx.x * blockDim.x + threadIdx.x;
    size_t tot = (size_t)NV * HIDDEN / 4;
    size_t lim = (size_t)N_NODES * HIDDEN / 4;
    if (i < tot) xv[i] = (i < lim) ? x[i] : make_float4(0.f, 0.f, 0.f, 0.f);
}
__global__ void k_pack_qkv(const float* __restrict__ wq, const float* __restrict__ wk,
                           const float* __restrict__ wv, const float* __restrict__ bq,
                           const float* __restrict__ bk, const float* __restrict__ bv,
                           float* __restrict__ wout, float* __restrict__ bout) {
    int i = blockIdx.x * blockDim.x + threadIdx.x;
    if (i < HIDDEN * QKVN) {
        int k = i / QKVN, n = i % QKVN;
        const float* src = (n < 128) ? wq : (n < 256 ? wk : wv);
        wout[i] = src[k * HIDDEN + (n & 127)];
    }
    if (i < QKVN) {
        const float* bs = (i < 128) ? bq : (i < 256 ? bk : bv);
        bout[i] = bs[i & 127];
    }
}

// ---------------------------------------------------------------------------
// Local CSR build: histogram -> fast shuffle scan -> scatter
// ---------------------------------------------------------------------------
__global__ void k_hist(const int* __restrict__ dst, int E, int* __restrict__ cnt) {
    int e = blockIdx.x * blockDim.x + threadIdx.x;
    if (e < E) atomicAdd(&cnt[dst[e]], 1);
}
// single-block two-level warp-shuffle inclusive scan, chunked
__global__ void k_scan(const int* __restrict__ cnt, int* __restrict__ rowptr, int n) {
    __shared__ int wsum[32];
    __shared__ int carry_s;
    const int tid = threadIdx.x;
    const int lane = tid & 31;
    const int wid = tid >> 5;
    if (tid == 0) carry_s = 0;
    __syncthreads();
    for (int base = 0; base < n; base += 1024) {
        int i = base + tid;
        int x = (i < n) ? cnt[i] : 0;
        #pragma unroll
        for (int off = 1; off < 32; off <<= 1) {
            int t = __shfl_up_sync(0xffffffffu, x, off);
            if (lane >= off) x += t;
        }
        if (lane == 31) wsum[wid] = x;
        __syncthreads();
        if (wid == 0) {
            int y = wsum[lane];
            #pragma unroll
            for (int off = 1; off < 32; off <<= 1) {
                int t = __shfl_up_sync(0xffffffffu, y, off);
                if (lane >= off) y += t;
            }
            wsum[lane] = y;
        }
        __syncthreads();
        int blockoff = (wid > 0) ? wsum[wid - 1] : 0;
        int carry = carry_s;
        if (i < n) rowptr[i + 1] = x + blockoff + carry;
        __syncthreads();
        if (tid == 1023) carry_s = carry + blockoff + x;  // == carry + chunk total
        __syncthreads();
    }
    if (tid == 0) rowptr[0] = 0;
}
__global__ void k_scatter(const int* __restrict__ src, const int* __restrict__ dst,
                          int E, int* __restrict__ cursor, int* __restrict__ esrc) {
    int e = blockIdx.x * blockDim.x + threadIdx.x;
    if (e < E) {
        int pos = atomicAdd(&cursor[dst[e]], 1);
        esrc[pos] = src[e];
    }
}
// Expander: every node has in-degree exactly 4 (group g = e/NV contributes one
// in-edge per node). Deterministic slot, no atomics, no scan.
__global__ void k_build_exp(const int* __restrict__ src, const int* __restrict__ dst,
                            int* __restrict__ esrc) {
    int e = blockIdx.x * blockDim.x + threadIdx.x;
    if (e < E_EXP) {
        int g = e / NV;
        esrc[dst[e] * 4 + g] = src[e];
    }
}

// ---------------------------------------------------------------------------
// Tensor-core GEMM (bf16 hi/lo split, fp32 accumulate)
//   mode 0: C = r;  mode 1: C += r;  mode 2: C = gelu(r);  mode 3: C = R + r
//   out2 (optional): rows < N_NODES of result also written there (N must be 128)
// ---------------------------------------------------------------------------
#define BM 128
#define BN 128
#define BK 32
#define APAD 8
#define BPAD 8

__device__ __forceinline__ void ldsm_x4(uint32_t* r, const void* p) {
    uint32_t a = (uint32_t)__cvta_generic_to_shared(p);
    asm volatile("ldmatrix.sync.aligned.m8n8.x4.shared.b16 {%0,%1,%2,%3}, [%4];"
                 : "=r"(r[0]), "=r"(r[1]), "=r"(r[2]), "=r"(r[3]) : "r"(a));
}
__device__ __forceinline__ void ldsm_x4t(uint32_t* r, const void* p) {
    uint32_t a = (uint32_t)__cvta_generic_to_shared(p);
    asm volatile("ldmatrix.sync.aligned.m8n8.x4.trans.shared.b16 {%0,%1,%2,%3}, [%4];"
                 : "=r"(r[0]), "=r"(r[1]), "=r"(r[2]), "=r"(r[3]) : "r"(a));
}
__device__ __forceinline__ void mma_bf16(float* c, const uint32_t* a, const uint32_t* b) {
    asm volatile("mma.sync.aligned.m16n8k16.row.col.f32.bf16.bf16.f32 "
                 "{%0,%1,%2,%3}, {%4,%5,%6,%7}, {%8,%9}, {%0,%1,%2,%3};"
                 : "+f"(c[0]), "+f"(c[1]), "+f"(c[2]), "+f"(c[3])
                 : "r"(a[0]), "r"(a[1]), "r"(a[2]), "r"(a[3]), "r"(b[0]), "r"(b[1]));
}
__device__ __forceinline__ void split2(float x, __nv_bfloat16& h, __nv_bfloat16& l) {
    h = __float2bfloat16_rn(x);
    l = __float2bfloat16_rn(x - __bfloat162float(h));
}

__global__ __launch_bounds__(256) void k_hgemm(
    const float* __restrict__ A, const float* __restrict__ B,
    const float* __restrict__ bias, float* __restrict__ C,
    const float* __restrict__ R, float* __restrict__ out2,
    int M, int N, int K, int mode)
{
    __shared__ __align__(16) __nv_bfloat16 Ahi[BM][BK + APAD];
    __shared__ __align__(16) __nv_bfloat16 Alo[BM][BK + APAD];
    __shared__ __align__(16) __nv_bfloat16 Bhi[BK][BN + BPAD];
    __shared__ __align__(16) __nv_bfloat16 Blo[BK][BN + BPAD];

    const int bm = blockIdx.y * BM;
    const int bn = blockIdx.x * BN;
    const int tid = threadIdx.x;
    const int lane = tid & 31;
    const int w = tid >> 5;
    const int wm = w & 3;
    const int wn = w >> 2;

    const int ar0 = tid >> 3;
    const int ac  = (tid & 7) << 2;
    const int br0 = tid >> 5;
    const int bc  = (tid & 31) << 2;

    float acc[2][8][4];
    #pragma unroll
    for (int i = 0; i < 2; i++)
        #pragma unroll
        for (int j = 0; j < 8; j++)
            #pragma unroll
            for (int t = 0; t < 4; t++) acc[i][j][t] = 0.0f;

    for (int k0 = 0; k0 < K; k0 += BK) {
        #pragma unroll
        for (int p = 0; p < 4; p++) {
            int r = ar0 + p * 32;
            float4 v = make_float4(0.f, 0.f, 0.f, 0.f);
            if (bm + r < M) v = *(const float4*)(A + (size_t)(bm + r) * K + k0 + ac);
            __nv_bfloat16 h, l;
            split2(v.x, h, l); Ahi[r][ac + 0] = h; Alo[r][ac + 0] = l;
            split2(v.y, h, l); Ahi[r][ac + 1] = h; Alo[r][ac + 1] = l;
            split2(v.z, h, l); Ahi[r][ac + 2] = h; Alo[r][ac + 2] = l;
            split2(v.w, h, l); Ahi[r][ac + 3] = h; Alo[r][ac + 3] = l;
        }
        #pragma unroll
        for (int p = 0; p < 4; p++) {
            int r = br0 + p * 8;
            float4 v = *(const float4*)(B + (size_t)(k0 + r) * N + bn + bc);
            __nv_bfloat16 h, l;
            split2(v.x, h, l); Bhi[r][bc + 0] = h; Blo[r][bc + 0] = l;
            split2(v.y, h, l); Bhi[r][bc + 1] = h; Blo[r][bc + 1] = l;
            split2(v.z, h, l); Bhi[r][bc + 2] = h; Blo[r][bc + 2] = l;
            split2(v.w, h, l); Bhi[r][bc + 3] = h; Blo[r][bc + 3] = l;
        }
        __syncthreads();

        #pragma unroll
        for (int ks = 0; ks < 2; ks++) {
            uint32_t ahi[2][4], alo[2][4], bhi[8][2], blo[8][2];
            #pragma unroll
            for (int mt = 0; mt < 2; mt++) {
                const int rr = wm * 32 + mt * 16 + (lane & 15);
                const int cc = ks * 16 + ((lane >> 4) << 3);
                ldsm_x4(ahi[mt], &Ahi[rr][cc]);
                ldsm_x4(alo[mt], &Alo[rr][cc]);
            }
            #pragma unroll
            for (int nt = 0; nt < 4; nt++) {
                const int rr = ks * 16 + (lane & 15);
                const int cc = wn * 64 + nt * 16 + ((lane >> 4) << 3);
                uint32_t th[4], tl[4];
                ldsm_x4t(th, &Bhi[rr][cc]);
                ldsm_x4t(tl, &Blo[rr][cc]);
                bhi[nt * 2][0] = th[0]; bhi[nt * 2][1] = th[1];
                bhi[nt * 2 + 1][0] = th[2]; bhi[nt * 2 + 1][1] = th[3];
                blo[nt * 2][0] = tl[0]; blo[nt * 2][1] = tl[1];
                blo[nt * 2 + 1][0] = tl[2]; blo[nt * 2 + 1][1] = tl[3];
            }
            #pragma unroll
            for (int mt = 0; mt < 2; mt++)
                #pragma unroll
                for (int nb = 0; nb < 8; nb++) {
                    mma_bf16(acc[mt][nb], ahi[mt], bhi[nb]);
                    mma_bf16(acc[mt][nb], ahi[mt], blo[nb]);
                    mma_bf16(acc[mt][nb], alo[mt], bhi[nb]);
                }
        }
        __syncthreads();
    }

    const int g = lane >> 2;
    const int t4 = lane & 3;
    #pragma unroll
    for (int mt = 0; mt < 2; mt++) {
        #pragma unroll
        for (int nb = 0; nb < 8; nb++) {
            int col = bn + wn * 64 + nb * 8 + t4 * 2;
            float b0 = bias[col], b1 = bias[col + 1];
            #pragma unroll
            for (int half = 0; half < 2; half++) {
                int row = bm + wm * 32 + mt * 16 + g + half * 8;
                if (row >= M) continue;
                float v0 = acc[mt][nb][half * 2 + 0] + b0;
                float v1 = acc[mt][nb][half * 2 + 1] + b1;
                float* cp = C + (size_t)row * N + col;
                if (mode == 1) {
                    float2 old = *(const float2*)cp;
                    v0 += old.x; v1 += old.y;
                } else if (mode == 2) {
                    v0 = 0.5f * v0 * (1.0f + erff(v0 * 0.70710678118654752440f));
                    v1 = 0.5f * v1 * (1.0f + erff(v1 * 0.70710678118654752440f));
                } else if (mode == 3) {
                    float2 rr = *(const float2*)(R + (size_t)row * N + col);
                    v0 += rr.x; v1 += rr.y;
                }
                *(float2*)cp = make_float2(v0, v1);
                if (out2 && row < N_NODES)
                    *(float2*)(out2 + (size_t)row * N + col) = make_float2(v0, v1);
            }
        }
    }
}

// ---------------------------------------------------------------------------
// Fused gather attention: one warp per destination node.
// fixedDeg != 0 -> implicit rowptr (beg = d*fixedDeg); addVN adds implicit
// in-edge from the virtual node.
// ---------------------------------------------------------------------------
__global__ void k_gather(const float* __restrict__ qkv, float* __restrict__ agg,
                         const int* __restrict__ rowptr, const int* __restrict__ esrc,
                         int nDst, int addVN, int vnid, int fixedDeg)
{
    int d = (blockIdx.x * blockDim.x + threadIdx.x) >> 5;
    int lane = threadIdx.x & 31;
    if (d >= nDst) return;

    float4 qd = *(const float4*)(qkv + (size_t)d * QKVN + lane * 4);
    float4 vacc = make_float4(0.f, 0.f, 0.f, 0.f);
    float ssum = 0.0f;

    int beg, end;
    if (fixedDeg) { beg = d * fixedDeg; end = beg + fixedDeg; }
    else          { beg = rowptr[d];    end = rowptr[d + 1];  }

    for (int e = beg; e <= end; e++) {
        int s;
        if (e < end) s = esrc[e];
        else if (addVN) s = vnid;
        else break;
        const float* row = qkv + (size_t)s * QKVN;
        float4 ka = *(const float4*)(row + 128 + lane * 4);
        float dp = qd.x * ka.x + qd.y * ka.y + qd.z * ka.z + qd.w * ka.w;
        dp += __shfl_xor_sync(0xffffffffu, dp, 1);
        dp += __shfl_xor_sync(0xffffffffu, dp, 2);
        float ex = __expf(dp * 0.25f);
        float4 va = *(const float4*)(row + 256 + lane * 4);
        vacc.x = fmaf(ex, va.x, vacc.x);
        vacc.y = fmaf(ex, va.y, vacc.y);
        vacc.z = fmaf(ex, va.z, vacc.z);
        vacc.w = fmaf(ex, va.w, vacc.w);
        ssum += ex;
    }
    float inv = 1.0f / (ssum + 1e-16f);
    *(float4*)(agg + (size_t)d * HIDDEN + lane * 4) =
        make_float4(vacc.x * inv, vacc.y * inv, vacc.z * inv, vacc.w * inv);
}

// ---------------------------------------------------------------------------
// Virtual-node destination (local graph): in-edges are src=0..n-1
// ---------------------------------------------------------------------------
__device__ __forceinline__ void red_add_v4(float* p, float x, float y, float z, float w) {
    asm volatile("red.global.add.v4.f32 [%0], {%1, %2, %3, %4};"
                 :: "l"(p), "f"(x), "f"(y), "f"(z), "f"(w) : "memory");
}

__global__ void k_vn_partial(const float* __restrict__ qkv,
                             float* __restrict__ vnacc, float* __restrict__ vnsum,
                             int vnid)
{
    int warp = (blockIdx.x * blockDim.x + threadIdx.x) >> 5;
    int lane = threadIdx.x & 31;
    int nwarps = (gridDim.x * blockDim.x) >> 5;

    float4 qd = *(const float4*)(qkv + (size_t)vnid * QKVN + lane * 4);
    float4 vacc = make_float4(0.f, 0.f, 0.f, 0.f);
    float ssum = 0.0f;

    for (int s = warp; s < N_NODES; s += nwarps) {
        const float* row = qkv + (size_t)s * QKVN;
        float4 ka = *(const float4*)(row + 128 + lane * 4);
        float dp = qd.x * ka.x + qd.y * ka.y + qd.z * ka.z + qd.w * ka.w;
        dp += __shfl_xor_sync(0xffffffffu, dp, 1);
        dp += __shfl_xor_sync(0xffffffffu, dp, 2);
        float ex = __expf(dp * 0.25f);
        float4 va = *(const float4*)(row + 256 + lane * 4);
        vacc.x = fmaf(ex, va.x, vacc.x);
        vacc.y = fmaf(ex, va.y, vacc.y);
        vacc.z = fmaf(ex, va.z, vacc.z);
        vacc.w = fmaf(ex, va.w, vacc.w);
        ssum += ex;
    }
    red_add_v4(vnacc + lane * 4, vacc.x, vacc.y, vacc.z, vacc.w);
    if ((lane & 3) == 0) atomicAdd(&vnsum[lane >> 2], ssum);
}

__global__ void k_vn_final(const float* __restrict__ vnacc, const float* __restrict__ vnsum,
                           float* __restrict__ agg, int vnid)
{
    int lane = threadIdx.x & 31;
    if (threadIdx.x >= 32) return;
    float inv = 1.0f / (vnsum[lane >> 2] + 1e-16f);
    float4 v = *(const float4*)(vnacc + lane * 4);
    *(float4*)(agg + (size_t)vnid * HIDDEN + lane * 4) =
        make_float4(v.x * inv, v.y * inv, v.z * inv, v.w * inv);
}

// ---------------------------------------------------------------------------
// LayerNorm
// ---------------------------------------------------------------------------
__global__ void k_layernorm(const float* __restrict__ in, const float* __restrict__ g,
                            const float* __restrict__ b, float* __restrict__ out, int M)
{
    int row = blockIdx.x * (blockDim.x >> 5) + (threadIdx.x >> 5);
    int lane = threadIdx.x & 31;
    if (row >= M) return;
    const float* p = in + (size_t)row * HIDDEN;
    float vals[4], s = 0.0f, s2 = 0.0f;
    #pragma unroll
    for (int i = 0; i < 4; i++) {
        float v = p[lane + i * 32];
        vals[i] = v; s += v; s2 += v * v;
    }
    #pragma unroll
    for (int o = 16; o; o >>= 1) {
        s  += __shfl_xor_sync(0xffffffffu, s,  o);
        s2 += __shfl_xor_sync(0xffffffffu, s2, o);
    }
    float mu  = s * (1.0f / HIDDEN);
    float var = s2 * (1.0f / HIDDEN) - mu * mu;
    float inv = rsqrtf(var + 1e-5f);
    #pragma unroll
    for (int i = 0; i < 4; i++) {
        int c = lane + i * 32;
        out[(size_t)row * HIDDEN + c] = (vals[i] - mu) * inv * g[c] + b[c];
    }
}

// ---------------------------------------------------------------------------
// Host-side orchestration
// ---------------------------------------------------------------------------
static inline dim3 grid1(size_t n, int bs) { return dim3((unsigned)((n + bs - 1) / bs)); }

static void launch_gemm(const float* A, const float* B, const float* bias, float* C,
                        const float* R, float* out2, int M, int N, int K, int mode) {
    dim3 g(N / BN, (M + BM - 1) / BM);
    k_hgemm<<<g, 256>>>(A, B, bias, C, R, out2, M, N, K, mode);
}

extern "C" void kernel_launch(void* const* d_in, const int* in_sizes, int n_in,
                              void* d_out, int out_size)
{
    (void)n_in; (void)in_sizes; (void)out_size;
    const float* x         = (const float*)d_in[0];
    const int*   edge_idx  = (const int*)  d_in[1];
    const int*   exp_edges = (const int*)  d_in[2];
    const float* lq_w = (const float*)d_in[3];   const float* lq_b = (const float*)d_in[4];
    const float* lk_w = (const float*)d_in[5];   const float* lk_b = (const float*)d_in[6];
    const float* lv_w = (const float*)d_in[7];   const float* lv_b = (const float*)d_in[8];
    const float* lo_w = (const float*)d_in[9];   const float* lo_b = (const float*)d_in[10];
    const float* eq_w = (const float*)d_in[11];  const float* eq_b = (const float*)d_in[12];
    const float* ek_w = (const float*)d_in[13];  const float* ek_b = (const float*)d_in[14];
    const float* ev_w = (const float*)d_in[15];  const float* ev_b = (const float*)d_in[16];
    const float* eo_w = (const float*)d_in[17];  const float* eo_b = (const float*)d_in[18];
    const float* ln_g = (const float*)d_in[19];  const float* ln_b = (const float*)d_in[20];
    const float* ffn_w1 = (const float*)d_in[21]; const float* ffn_b1 = (const float*)d_in[22];
    const float* ffn_w2 = (const float*)d_in[23]; const float* ffn_b2 = (const float*)d_in[24];

    float *xv, *acc, *qkv, *agg, *h1, *wqkv, *bqkv, *vnacc, *vnsum;
    int *cnt, *rowptrL, *esrcL, *esrcE, *cursor;
    cudaGetSymbolAddress((void**)&xv,      g_xv);
    cudaGetSymbolAddress((void**)&acc,     g_acc);
    cudaGetSymbolAddress((void**)&qkv,     g_qkv);
    cudaGetSymbolAddress((void**)&agg,     g_agg);
    cudaGetSymbolAddress((void**)&h1,      g_h1);
    cudaGetSymbolAddress((void**)&wqkv,    g_wqkv);
    cudaGetSymbolAddress((void**)&bqkv,    g_bqkv);
    cudaGetSymbolAddress((void**)&vnacc,   g_vnacc);
    cudaGetSymbolAddress((void**)&vnsum,   g_vnsum);
    cudaGetSymbolAddress((void**)&cnt,     g_cnt);
    cudaGetSymbolAddress((void**)&rowptrL, g_rowptrL);
    cudaGetSymbolAddress((void**)&esrcL,   g_esrcL);
    cudaGetSymbolAddress((void**)&esrcE,   g_esrcE);
    cudaGetSymbolAddress((void**)&cursor,  g_cursor);

    const size_t nvh = (size_t)NV * HIDDEN;

    k_build_xv<<<grid1(nvh / 4, 256), 256>>>((const float4*)x, (float4*)xv);

    // Local CSR (once per call)
    k_zero_i<<<grid1(NV, 256), 256>>>(cnt, NV);
    k_hist<<<grid1(N_EDGES, 256), 256>>>(edge_idx + N_EDGES, N_EDGES, cnt);
    k_scan<<<1, 1024>>>(cnt, rowptrL, NV);
    k_copy_i<<<grid1(NV, 256), 256>>>(cursor, rowptrL, NV);
    k_scatter<<<grid1(N_EDGES, 256), 256>>>(edge_idx, edge_idx + N_EDGES, N_EDGES,
                                            cursor, esrcL);

    for (int l = 0; l < LAYERS; l++) {
        // ----- local attention: acc = xv + O(attn_local(xv)) -----
        k_pack_qkv<<<grid1(HIDDEN * QKVN, 256), 256>>>(
            lq_w + (size_t)l * HIDDEN * HIDDEN, lk_w + (size_t)l * HIDDEN * HIDDEN,
            lv_w + (size_t)l * HIDDEN * HIDDEN,
            lq_b + (size_t)l * HIDDEN, lk_b + (size_t)l * HIDDEN, lv_b + (size_t)l * HIDDEN,
            wqkv, bqkv);
        launch_gemm(xv, wqkv, bqkv, qkv, nullptr, nullptr, NV, QKVN, HIDDEN, 0);

        k_gather<<<grid1((size_t)N_NODES * 32, 256), 256>>>(
            qkv, agg, rowptrL, esrcL, N_NODES, /*addVN=*/1, N_NODES, /*fixedDeg=*/0);
        k_zero_vn<<<1, 128>>>(vnacc, vnsum);
        k_vn_partial<<<128, 256>>>(qkv, vnacc, vnsum, N_NODES);
        k_vn_final<<<1, 32>>>(vnacc, vnsum, agg, N_NODES);

        launch_gemm(agg, lo_w + (size_t)l * HIDDEN * HIDDEN, lo_b + (size_t)l * HIDDEN,
                    acc, xv, nullptr, NV, HIDDEN, HIDDEN, /*mode=*/3);

        // ----- expander attention: acc += O(attn_exp(xv)) -----
        const int* esrc_in = exp_edges + (size_t)l * 2 * E_EXP;
        const int* edst_in = esrc_in + E_EXP;
        k_build_exp<<<grid1(E_EXP, 256), 256>>>(esrc_in, edst_in, esrcE);

        k_pack_qkv<<<grid1(HIDDEN * QKVN, 256), 256>>>(
            eq_w + (size_t)l * HIDDEN * HIDDEN, ek_w + (size_t)l * HIDDEN * HIDDEN,
            ev_w + (size_t)l * HIDDEN * HIDDEN,
            eq_b + (size_t)l * HIDDEN, ek_b + (size_t)l * HIDDEN, ev_b + (size_t)l * HIDDEN,
            wqkv, bqkv);
        launch_gemm(xv, wqkv, bqkv, qkv, nullptr, nullptr, NV, QKVN, HIDDEN, 0);

        k_gather<<<grid1((size_t)NV * 32, 256), 256>>>(
            qkv, agg, nullptr, esrcE, NV, /*addVN=*/0, N_NODES, /*fixedDeg=*/4);

        launch_gemm(agg, eo_w + (size_t)l * HIDDEN * HIDDEN, eo_b + (size_t)l * HIDDEN,
                    acc, nullptr, nullptr, NV, HIDDEN, HIDDEN, /*mode=*/1);

        // ----- LN -----
        {
            int wpb = 8;
            dim3 g((NV + wpb - 1) / wpb);
            k_layernorm<<<g, wpb * 32>>>(acc, ln_g + (size_t)l * HIDDEN,
                                         ln_b + (size_t)l * HIDDEN, xv, NV);
        }

        // ----- FFN (last layer writes rows < N_NODES to d_out too) -----
        launch_gemm(xv, ffn_w1 + (size_t)l * HIDDEN * 4 * HIDDEN,
                    ffn_b1 + (size_t)l * 4 * HIDDEN, h1, nullptr, nullptr,
                    NV, 4 * HIDDEN, HIDDEN, 2);
        launch_gemm(h1, ffn_w2 + (size_t)l * 4 * HIDDEN * HIDDEN,
                    ffn_b2 + (size_t)l * HIDDEN, xv, nullptr,
                    (l == LAYERS - 1) ? (float*)d_out : nullptr,
                    NV, HIDDEN, 4 * HIDDEN, 1);
    }
}

// round 6
// speedup vs baseline: 4.6431x; 1.0292x over previous
#include <cuda_runtime.h>
#include <cuda_bf16.h>
#include <math.h>
#include <stdint.h>

// ---------------------------------------------------------------------------
// Problem constants
// ---------------------------------------------------------------------------
#define N_NODES 20000
#define N_EDGES 320000
#define HIDDEN  128
#define HEADS   8
#define LAYERS  3
#define NV      (N_NODES + 1)
#define E_EXP   (NV * 4)                 // 80004 per layer
#define QKV6    (6 * HIDDEN)             // 768: lq|lk|lv|eq|ek|ev

// ---------------------------------------------------------------------------
// Scratch (device globals; no allocations)
// ---------------------------------------------------------------------------
__device__ float g_xv   [(size_t)NV * HIDDEN];
__device__ float g_acc  [(size_t)NV * HIDDEN];
__device__ float g_qkv  [(size_t)NV * QKV6];          // 61 MB
__device__ float g_agg  [(size_t)NV * 256];           // [local 128 | exp 128]
__device__ float g_h1   [(size_t)NV * 4 * HIDDEN];
// packed weights for all layers
__device__ float g_wqkv [(size_t)LAYERS * HIDDEN * QKV6];
__device__ float g_bqkv [LAYERS * QKV6];
__device__ float g_wo   [(size_t)LAYERS * 256 * HIDDEN];
__device__ float g_bo   [LAYERS * HIDDEN];
// CSR scratch
__device__ int   g_cnt    [NV];
__device__ int   g_rowptrL[NV + 1];
__device__ int   g_esrcL  [N_EDGES];
__device__ int   g_esrcE  [LAYERS * E_EXP];
__device__ int   g_cursor [NV];
__device__ int   g_bsum   [32];
// virtual-node reduction scratch: 512 warp slots, no atomics
#define VN_SLOTS 512
__device__ float g_vnacc2[VN_SLOTS * HIDDEN];
__device__ float g_vnsum2[VN_SLOTS * HEADS];

// ---------------------------------------------------------------------------
// Utility kernels
// ---------------------------------------------------------------------------
__global__ void k_zero_i(int* p, int n) {
    int i = blockIdx.x * blockDim.x + threadIdx.x;
    if (i < n) p[i] = 0;
}
__global__ void k_build_xv(const float4* __restrict__ x, float4* __restrict__ xv) {
    size_t i = (size_t)blockIdx.x * blockDim.x + threadIdx.x;
    size_t tot = (size_t)NV * HIDDEN / 4;
    size_t lim = (size_t)N_NODES * HIDDEN / 4;
    if (i < tot) xv[i] = (i < lim) ? x[i] : make_float4(0.f, 0.f, 0.f, 0.f);
}

// Pack all layers' weights once:
//   wqkv[l][k][n], n: 0-127 lq, 128-255 lk, 256-383 lv, 384-511 eq, 512-639 ek, 640-767 ev
//   wo[l][k][n]: k<128 -> lo_w[k][n], else eo_w[k-128][n];  bo = lo_b + eo_b
__global__ void k_pack_all(
    const float* __restrict__ lq_w, const float* __restrict__ lk_w,
    const float* __restrict__ lv_w, const float* __restrict__ eq_w,
    const float* __restrict__ ek_w, const float* __restrict__ ev_w,
    const float* __restrict__ lq_b, const float* __restrict__ lk_b,
    const float* __restrict__ lv_b, const float* __restrict__ eq_b,
    const float* __restrict__ ek_b, const float* __restrict__ ev_b,
    const float* __restrict__ lo_w, const float* __restrict__ eo_w,
    const float* __restrict__ lo_b, const float* __restrict__ eo_b,
    float* __restrict__ wqkv, float* __restrict__ bqkv,
    float* __restrict__ wo, float* __restrict__ bo)
{
    int i = blockIdx.x * blockDim.x + threadIdx.x;
    const int NQ = LAYERS * HIDDEN * QKV6;          // 294912
    if (i < NQ) {
        int l = i / (HIDDEN * QKV6);
        int r = i % (HIDDEN * QKV6);
        int k = r / QKV6, n = r % QKV6;
        int sel = n >> 7, c = n & 127;
        const float* w[6] = {lq_w, lk_w, lv_w, eq_w, ek_w, ev_w};
        wqkv[i] = w[sel][(size_t)l * HIDDEN * HIDDEN + k * HIDDEN + c];
    }
    if (i < LAYERS * 256 * HIDDEN) {                // 98304
        int l = i / (256 * HIDDEN);
        int r = i % (256 * HIDDEN);
        int k = r / HIDDEN, n = r % HIDDEN;
        wo[i] = (k < 128)
            ? lo_w[(size_t)l * HIDDEN * HIDDEN + k * HIDDEN + n]
            : eo_w[(size_t)l * HIDDEN * HIDDEN + (k - 128) * HIDDEN + n];
    }
    if (i < LAYERS * QKV6) {                        // 2304
        int l = i / QKV6, n = i % QKV6;
        int sel = n >> 7, c = n & 127;
        const float* b[6] = {lq_b, lk_b, lv_b, eq_b, ek_b, ev_b};
        bqkv[i] = b[sel][l * HIDDEN + c];
    }
    if (i < LAYERS * HIDDEN) {
        int l = i / HIDDEN, n = i % HIDDEN;
        bo[i] = lo_b[l * HIDDEN + n] + eo_b[l * HIDDEN + n];
    }
}

// ---------------------------------------------------------------------------
// Local CSR build: histogram -> 3-phase multi-block scan -> scatter
// ---------------------------------------------------------------------------
__global__ void k_hist(const int* __restrict__ dst, int E, int* __restrict__ cnt) {
    int e = blockIdx.x * blockDim.x + threadIdx.x;
    if (e < E) atomicAdd(&cnt[dst[e]], 1);
}
__global__ void k_scan1(const int* __restrict__ cnt, int* __restrict__ rowptr,
                        int* __restrict__ bsum, int n) {
    __shared__ int wsum[32];
    const int tid = threadIdx.x, lane = tid & 31, wid = tid >> 5;
    int i = blockIdx.x * 1024 + tid;
    int x = (i < n) ? cnt[i] : 0;
    #pragma unroll
    for (int off = 1; off < 32; off <<= 1) {
        int t = __shfl_up_sync(0xffffffffu, x, off);
        if (lane >= off) x += t;
    }
    if (lane == 31) wsum[wid] = x;
    __syncthreads();
    if (wid == 0) {
        int y = wsum[lane];
        #pragma unroll
        for (int off = 1; off < 32; off <<= 1) {
            int t = __shfl_up_sync(0xffffffffu, y, off);
            if (lane >= off) y += t;
        }
        wsum[lane] = y;
    }
    __syncthreads();
    int total = x + ((wid > 0) ? wsum[wid - 1] : 0);
    if (i < n) rowptr[i + 1] = total;
    if (tid == 1023) bsum[blockIdx.x] = total;
}
__global__ void k_scan2(int* __restrict__ bsum, int nb) {
    int lane = threadIdx.x;
    int v = (lane < nb) ? bsum[lane] : 0;
    int orig = v;
    #pragma unroll
    for (int off = 1; off < 32; off <<= 1) {
        int t = __shfl_up_sync(0xffffffffu, v, off);
        if (lane >= off) v += t;
    }
    if (lane < nb) bsum[lane] = v - orig;   // exclusive
}
__global__ void k_scan3(int* __restrict__ rowptr, const int* __restrict__ bsum,
                        const int* __restrict__ cnt, int* __restrict__ cursor, int n) {
    int i = blockIdx.x * blockDim.x + threadIdx.x;
    if (i < n) {
        int v = rowptr[i + 1] + bsum[i >> 10];
        rowptr[i + 1] = v;
        cursor[i] = v - cnt[i];
        if (i == 0) rowptr[0] = 0;
    }
}
__global__ void k_scatter(const int* __restrict__ src, const int* __restrict__ dst,
                          int E, int* __restrict__ cursor, int* __restrict__ esrc) {
    int e = blockIdx.x * blockDim.x + threadIdx.x;
    if (e < E) {
        int pos = atomicAdd(&cursor[dst[e]], 1);
        esrc[pos] = src[e];
    }
}
// Expander for all layers at once: in-degree exactly 4 per node per layer.
__global__ void k_build_exp_all(const int* __restrict__ ee, int* __restrict__ esrc) {
    int e = blockIdx.x * blockDim.x + threadIdx.x;
    if (e < LAYERS * E_EXP) {
        int l = e / E_EXP, r = e % E_EXP;
        int g = r / NV;
        int src = ee[(size_t)l * 2 * E_EXP + r];
        int dst = ee[(size_t)l * 2 * E_EXP + E_EXP + r];
        esrc[(size_t)l * E_EXP + dst * 4 + g] = src;
    }
}

// ---------------------------------------------------------------------------
// Tensor-core GEMM (bf16 hi/lo split, fp32 accumulate)
//   mode 0: C = r;  1: C += r;  2: C = gelu(r);  3: C = R + r
//   out2: also write rows < N_NODES (used on final FFN2)
// ---------------------------------------------------------------------------
#define BM 128
#define BN 128
#define BK 32
#define APAD 8
#define BPAD 8

__device__ __forceinline__ void ldsm_x4(uint32_t* r, const void* p) {
    uint32_t a = (uint32_t)__cvta_generic_to_shared(p);
    asm volatile("ldmatrix.sync.aligned.m8n8.x4.shared.b16 {%0,%1,%2,%3}, [%4];"
                 : "=r"(r[0]), "=r"(r[1]), "=r"(r[2]), "=r"(r[3]) : "r"(a));
}
__device__ __forceinline__ void ldsm_x4t(uint32_t* r, const void* p) {
    uint32_t a = (uint32_t)__cvta_generic_to_shared(p);
    asm volatile("ldmatrix.sync.aligned.m8n8.x4.trans.shared.b16 {%0,%1,%2,%3}, [%4];"
                 : "=r"(r[0]), "=r"(r[1]), "=r"(r[2]), "=r"(r[3]) : "r"(a));
}
__device__ __forceinline__ void mma_bf16(float* c, const uint32_t* a, const uint32_t* b) {
    asm volatile("mma.sync.aligned.m16n8k16.row.col.f32.bf16.bf16.f32 "
                 "{%0,%1,%2,%3}, {%4,%5,%6,%7}, {%8,%9}, {%0,%1,%2,%3};"
                 : "+f"(c[0]), "+f"(c[1]), "+f"(c[2]), "+f"(c[3])
                 : "r"(a[0]), "r"(a[1]), "r"(a[2]), "r"(a[3]), "r"(b[0]), "r"(b[1]));
}
__device__ __forceinline__ void split2(float x, __nv_bfloat16& h, __nv_bfloat16& l) {
    h = __float2bfloat16_rn(x);
    l = __float2bfloat16_rn(x - __bfloat162float(h));
}

__global__ __launch_bounds__(256) void k_hgemm(
    const float* __restrict__ A, const float* __restrict__ B,
    const float* __restrict__ bias, float* __restrict__ C,
    const float* __restrict__ R, float* __restrict__ out2,
    int M, int N, int K, int mode)
{
    __shared__ __align__(16) __nv_bfloat16 Ahi[BM][BK + APAD];
    __shared__ __align__(16) __nv_bfloat16 Alo[BM][BK + APAD];
    __shared__ __align__(16) __nv_bfloat16 Bhi[BK][BN + BPAD];
    __shared__ __align__(16) __nv_bfloat16 Blo[BK][BN + BPAD];

    const int bm = blockIdx.y * BM;
    const int bn = blockIdx.x * BN;
    const int tid = threadIdx.x;
    const int lane = tid & 31;
    const int w = tid >> 5;
    const int wm = w & 3;
    const int wn = w >> 2;

    const int ar0 = tid >> 3;
    const int ac  = (tid & 7) << 2;
    const int br0 = tid >> 5;
    const int bc  = (tid & 31) << 2;

    float acc[2][8][4];
    #pragma unroll
    for (int i = 0; i < 2; i++)
        #pragma unroll
        for (int j = 0; j < 8; j++)
            #pragma unroll
            for (int t = 0; t < 4; t++) acc[i][j][t] = 0.0f;

    for (int k0 = 0; k0 < K; k0 += BK) {
        #pragma unroll
        for (int p = 0; p < 4; p++) {
            int r = ar0 + p * 32;
            float4 v = make_float4(0.f, 0.f, 0.f, 0.f);
            if (bm + r < M) v = *(const float4*)(A + (size_t)(bm + r) * K + k0 + ac);
            __nv_bfloat16 h, l;
            split2(v.x, h, l); Ahi[r][ac + 0] = h; Alo[r][ac + 0] = l;
            split2(v.y, h, l); Ahi[r][ac + 1] = h; Alo[r][ac + 1] = l;
            split2(v.z, h, l); Ahi[r][ac + 2] = h; Alo[r][ac + 2] = l;
            split2(v.w, h, l); Ahi[r][ac + 3] = h; Alo[r][ac + 3] = l;
        }
        #pragma unroll
        for (int p = 0; p < 4; p++) {
            int r = br0 + p * 8;
            float4 v = *(const float4*)(B + (size_t)(k0 + r) * N + bn + bc);
            __nv_bfloat16 h, l;
            split2(v.x, h, l); Bhi[r][bc + 0] = h; Blo[r][bc + 0] = l;
            split2(v.y, h, l); Bhi[r][bc + 1] = h; Blo[r][bc + 1] = l;
            split2(v.z, h, l); Bhi[r][bc + 2] = h; Blo[r][bc + 2] = l;
            split2(v.w, h, l); Bhi[r][bc + 3] = h; Blo[r][bc + 3] = l;
        }
        __syncthreads();

        #pragma unroll
        for (int ks = 0; ks < 2; ks++) {
            uint32_t ahi[2][4], alo[2][4], bhi[8][2], blo[8][2];
            #pragma unroll
            for (int mt = 0; mt < 2; mt++) {
                const int rr = wm * 32 + mt * 16 + (lane & 15);
                const int cc = ks * 16 + ((lane >> 4) << 3);
                ldsm_x4(ahi[mt], &Ahi[rr][cc]);
                ldsm_x4(alo[mt], &Alo[rr][cc]);
            }
            #pragma unroll
            for (int nt = 0; nt < 4; nt++) {
                const int rr = ks * 16 + (lane & 15);
                const int cc = wn * 64 + nt * 16 + ((lane >> 4) << 3);
                uint32_t th[4], tl[4];
                ldsm_x4t(th, &Bhi[rr][cc]);
                ldsm_x4t(tl, &Blo[rr][cc]);
                bhi[nt * 2][0] = th[0]; bhi[nt * 2][1] = th[1];
                bhi[nt * 2 + 1][0] = th[2]; bhi[nt * 2 + 1][1] = th[3];
                blo[nt * 2][0] = tl[0]; blo[nt * 2][1] = tl[1];
                blo[nt * 2 + 1][0] = tl[2]; blo[nt * 2 + 1][1] = tl[3];
            }
            #pragma unroll
            for (int mt = 0; mt < 2; mt++)
                #pragma unroll
                for (int nb = 0; nb < 8; nb++) {
                    mma_bf16(acc[mt][nb], ahi[mt], bhi[nb]);
                    mma_bf16(acc[mt][nb], ahi[mt], blo[nb]);
                    mma_bf16(acc[mt][nb], alo[mt], bhi[nb]);
                }
        }
        __syncthreads();
    }

    const int g = lane >> 2;
    const int t4 = lane & 3;
    #pragma unroll
    for (int mt = 0; mt < 2; mt++) {
        #pragma unroll
        for (int nb = 0; nb < 8; nb++) {
            int col = bn + wn * 64 + nb * 8 + t4 * 2;
            float b0 = bias[col], b1 = bias[col + 1];
            #pragma unroll
            for (int half = 0; half < 2; half++) {
                int row = bm + wm * 32 + mt * 16 + g + half * 8;
                if (row >= M) continue;
                float v0 = acc[mt][nb][half * 2 + 0] + b0;
                float v1 = acc[mt][nb][half * 2 + 1] + b1;
                float* cp = C + (size_t)row * N + col;
                if (mode == 1) {
                    float2 old = *(const float2*)cp;
                    v0 += old.x; v1 += old.y;
                } else if (mode == 2) {
                    v0 = 0.5f * v0 * (1.0f + erff(v0 * 0.70710678118654752440f));
                    v1 = 0.5f * v1 * (1.0f + erff(v1 * 0.70710678118654752440f));
                } else if (mode == 3) {
                    float2 rr = *(const float2*)(R + (size_t)row * N + col);
                    v0 += rr.x; v1 += rr.y;
                }
                *(float2*)cp = make_float2(v0, v1);
                if (out2 && row < N_NODES)
                    *(float2*)(out2 + (size_t)row * N + col) = make_float2(v0, v1);
            }
        }
    }
}

// ---------------------------------------------------------------------------
// Combined gather: warps [0, N_NODES) do local attention (CSR + implicit vn
// in-edge) into agg[:, 0:128]; warps [N_NODES, N_NODES+NV) do expander
// attention (fixed degree 4) into agg[:, 128:256].
// qkv row layout: [lq | lk | lv | eq | ek | ev], stride 768.
// ---------------------------------------------------------------------------
__global__ void k_gather_both(const float* __restrict__ qkv, float* __restrict__ agg,
                              const int* __restrict__ rowptr,
                              const int* __restrict__ esrcL,
                              const int* __restrict__ esrcE)
{
    int wrp = (blockIdx.x * blockDim.x + threadIdx.x) >> 5;
    int lane = threadIdx.x & 31;
    const int total = N_NODES + NV;
    if (wrp >= total) return;

    const bool isExp = (wrp >= N_NODES);
    const int d = isExp ? (wrp - N_NODES) : wrp;
    const int qoff = isExp ? 384 : 0;
    const int* esrc = isExp ? esrcE : esrcL;

    float4 qd = *(const float4*)(qkv + (size_t)d * QKV6 + qoff + lane * 4);
    float4 vacc = make_float4(0.f, 0.f, 0.f, 0.f);
    float ssum = 0.0f;

    int beg, end, addVN;
    if (isExp) { beg = d * 4;      end = beg + 4;      addVN = 0; }
    else       { beg = rowptr[d];  end = rowptr[d + 1]; addVN = 1; }

    for (int e = beg; e <= end; e++) {
        int s;
        if (e < end) s = esrc[e];
        else if (addVN) s = N_NODES;
        else break;
        const float* row = qkv + (size_t)s * QKV6 + qoff;
        float4 ka = *(const float4*)(row + 128 + lane * 4);
        float dp = qd.x * ka.x + qd.y * ka.y + qd.z * ka.z + qd.w * ka.w;
        dp += __shfl_xor_sync(0xffffffffu, dp, 1);
        dp += __shfl_xor_sync(0xffffffffu, dp, 2);
        float ex = __expf(dp * 0.25f);
        float4 va = *(const float4*)(row + 256 + lane * 4);
        vacc.x = fmaf(ex, va.x, vacc.x);
        vacc.y = fmaf(ex, va.y, vacc.y);
        vacc.z = fmaf(ex, va.z, vacc.z);
        vacc.w = fmaf(ex, va.w, vacc.w);
        ssum += ex;
    }
    float inv = 1.0f / (ssum + 1e-16f);
    *(float4*)(agg + (size_t)d * 256 + (isExp ? 128 : 0) + lane * 4) =
        make_float4(vacc.x * inv, vacc.y * inv, vacc.z * inv, vacc.w * inv);
}

// ---------------------------------------------------------------------------
// Virtual-node (local attention dst): per-warp slots, no atomics.
// ---------------------------------------------------------------------------
__global__ void k_vn_partial(const float* __restrict__ qkv,
                             float* __restrict__ vnacc2, float* __restrict__ vnsum2)
{
    int wrp = (blockIdx.x * blockDim.x + threadIdx.x) >> 5;   // 0..VN_SLOTS-1
    int lane = threadIdx.x & 31;

    float4 qd = *(const float4*)(qkv + (size_t)N_NODES * QKV6 + lane * 4);
    float4 vacc = make_float4(0.f, 0.f, 0.f, 0.f);
    float ssum = 0.0f;

    for (int s = wrp; s < N_NODES; s += VN_SLOTS) {
        const float* row = qkv + (size_t)s * QKV6;
        float4 ka = *(const float4*)(row + 128 + lane * 4);
        float dp = qd.x * ka.x + qd.y * ka.y + qd.z * ka.z + qd.w * ka.w;
        dp += __shfl_xor_sync(0xffffffffu, dp, 1);
        dp += __shfl_xor_sync(0xffffffffu, dp, 2);
        float ex = __expf(dp * 0.25f);
        float4 va = *(const float4*)(row + 256 + lane * 4);
        vacc.x = fmaf(ex, va.x, vacc.x);
        vacc.y = fmaf(ex, va.y, vacc.y);
        vacc.z = fmaf(ex, va.z, vacc.z);
        vacc.w = fmaf(ex, va.w, vacc.w);
        ssum += ex;
    }
    *(float4*)(vnacc2 + (size_t)wrp * HIDDEN + lane * 4) = vacc;
    if ((lane & 3) == 0) vnsum2[wrp * HEADS + (lane >> 2)] = ssum;
}

__global__ void k_vn_final(const float* __restrict__ vnacc2,
                           const float* __restrict__ vnsum2,
                           float* __restrict__ agg)
{
    int dim = threadIdx.x;      // 0..127
    if (dim >= HIDDEN) return;
    int head = dim >> 4;
    float acc = 0.0f, ssum = 0.0f;
    for (int s = 0; s < VN_SLOTS; s++) {
        acc  += vnacc2[(size_t)s * HIDDEN + dim];
        ssum += vnsum2[s * HEADS + head];
    }
    agg[(size_t)N_NODES * 256 + dim] = acc / (ssum + 1e-16f);
}

// ---------------------------------------------------------------------------
// LayerNorm
// ---------------------------------------------------------------------------
__global__ void k_layernorm(const float* __restrict__ in, const float* __restrict__ g,
                            const float* __restrict__ b, float* __restrict__ out, int M)
{
    int row = blockIdx.x * (blockDim.x >> 5) + (threadIdx.x >> 5);
    int lane = threadIdx.x & 31;
    if (row >= M) return;
    const float* p = in + (size_t)row * HIDDEN;
    float vals[4], s = 0.0f, s2 = 0.0f;
    #pragma unroll
    for (int i = 0; i < 4; i++) {
        float v = p[lane + i * 32];
        vals[i] = v; s += v; s2 += v * v;
    }
    #pragma unroll
    for (int o = 16; o; o >>= 1) {
        s  += __shfl_xor_sync(0xffffffffu, s,  o);
        s2 += __shfl_xor_sync(0xffffffffu, s2, o);
    }
    float mu  = s * (1.0f / HIDDEN);
    float var = s2 * (1.0f / HIDDEN) - mu * mu;
    float inv = rsqrtf(var + 1e-5f);
    #pragma unroll
    for (int i = 0; i < 4; i++) {
        int c = lane + i * 32;
        out[(size_t)row * HIDDEN + c] = (vals[i] - mu) * inv * g[c] + b[c];
    }
}

// ---------------------------------------------------------------------------
// Host-side orchestration
// ---------------------------------------------------------------------------
static inline dim3 grid1(size_t n, int bs) { return dim3((unsigned)((n + bs - 1) / bs)); }

static void launch_gemm(const float* A, const float* B, const float* bias, float* C,
                        const float* R, float* out2, int M, int N, int K, int mode) {
    dim3 g(N / BN, (M + BM - 1) / BM);
    k_hgemm<<<g, 256>>>(A, B, bias, C, R, out2, M, N, K, mode);
}

extern "C" void kernel_launch(void* const* d_in, const int* in_sizes, int n_in,
                              void* d_out, int out_size)
{
    (void)n_in; (void)in_sizes; (void)out_size;
    const float* x         = (const float*)d_in[0];
    const int*   edge_idx  = (const int*)  d_in[1];
    const int*   exp_edges = (const int*)  d_in[2];
    const float* lq_w = (const float*)d_in[3];   const float* lq_b = (const float*)d_in[4];
    const float* lk_w = (const float*)d_in[5];   const float* lk_b = (const float*)d_in[6];
    const float* lv_w = (const float*)d_in[7];   const float* lv_b = (const float*)d_in[8];
    const float* lo_w = (const float*)d_in[9];   const float* lo_b = (const float*)d_in[10];
    const float* eq_w = (const float*)d_in[11];  const float* eq_b = (const float*)d_in[12];
    const float* ek_w = (const float*)d_in[13];  const float* ek_b = (const float*)d_in[14];
    const float* ev_w = (const float*)d_in[15];  const float* ev_b = (const float*)d_in[16];
    const float* eo_w = (const float*)d_in[17];  const float* eo_b = (const float*)d_in[18];
    const float* ln_g = (const float*)d_in[19];  const float* ln_b = (const float*)d_in[20];
    const float* ffn_w1 = (const float*)d_in[21]; const float* ffn_b1 = (const float*)d_in[22];
    const float* ffn_w2 = (const float*)d_in[23]; const float* ffn_b2 = (const float*)d_in[24];

    float *xv, *acc, *qkv, *agg, *h1, *wqkv, *bqkv, *wo, *bo, *vnacc2, *vnsum2;
    int *cnt, *rowptrL, *esrcL, *esrcE, *cursor, *bsum;
    cudaGetSymbolAddress((void**)&xv,      g_xv);
    cudaGetSymbolAddress((void**)&acc,     g_acc);
    cudaGetSymbolAddress((void**)&qkv,     g_qkv);
    cudaGetSymbolAddress((void**)&agg,     g_agg);
    cudaGetSymbolAddress((void**)&h1,      g_h1);
    cudaGetSymbolAddress((void**)&wqkv,    g_wqkv);
    cudaGetSymbolAddress((void**)&bqkv,    g_bqkv);
    cudaGetSymbolAddress((void**)&wo,      g_wo);
    cudaGetSymbolAddress((void**)&bo,      g_bo);
    cudaGetSymbolAddress((void**)&vnacc2,  g_vnacc2);
    cudaGetSymbolAddress((void**)&vnsum2,  g_vnsum2);
    cudaGetSymbolAddress((void**)&cnt,     g_cnt);
    cudaGetSymbolAddress((void**)&rowptrL, g_rowptrL);
    cudaGetSymbolAddress((void**)&esrcL,   g_esrcL);
    cudaGetSymbolAddress((void**)&esrcE,   g_esrcE);
    cudaGetSymbolAddress((void**)&cursor,  g_cursor);
    cudaGetSymbolAddress((void**)&bsum,    g_bsum);

    const size_t nvh = (size_t)NV * HIDDEN;

    // ---- setup ----
    k_build_xv<<<grid1(nvh / 4, 256), 256>>>((const float4*)x, (float4*)xv);
    k_zero_i<<<grid1(NV, 256), 256>>>(cnt, NV);
    k_hist<<<grid1(N_EDGES, 256), 256>>>(edge_idx + N_EDGES, N_EDGES, cnt);
    {
        int nblk = (NV + 1023) / 1024;    // 20
        k_scan1<<<nblk, 1024>>>(cnt, rowptrL, bsum, NV);
        k_scan2<<<1, 32>>>(bsum, nblk);
        k_scan3<<<grid1(NV, 256), 256>>>(rowptrL, bsum, cnt, cursor, NV);
    }
    k_scatter<<<grid1(N_EDGES, 256), 256>>>(edge_idx, edge_idx + N_EDGES, N_EDGES,
                                            cursor, esrcL);
    k_build_exp_all<<<grid1((size_t)LAYERS * E_EXP, 256), 256>>>(exp_edges, esrcE);
    k_pack_all<<<grid1((size_t)LAYERS * HIDDEN * QKV6, 256), 256>>>(
        lq_w, lk_w, lv_w, eq_w, ek_w, ev_w,
        lq_b, lk_b, lv_b, eq_b, ek_b, ev_b,
        lo_w, eo_w, lo_b, eo_b,
        wqkv, bqkv, wo, bo);

    // ---- layers ----
    for (int l = 0; l < LAYERS; l++) {
        // fused qkv for both attentions: [NV, 768]
        launch_gemm(xv, wqkv + (size_t)l * HIDDEN * QKV6, bqkv + l * QKV6,
                    qkv, nullptr, nullptr, NV, QKV6, HIDDEN, 0);

        // combined gather (local + expander)
        k_gather_both<<<grid1((size_t)(N_NODES + NV) * 32, 256), 256>>>(
            qkv, agg, rowptrL, esrcL, esrcE + (size_t)l * E_EXP);
        k_vn_partial<<<VN_SLOTS / 8, 256>>>(qkv, vnacc2, vnsum2);
        k_vn_final<<<1, 128>>>(vnacc2, vnsum2, agg);

        // combined o-projection: acc = xv + [agg_l | agg_e] @ [wo_l; wo_e] + bo
        launch_gemm(agg, wo + (size_t)l * 256 * HIDDEN, bo + l * HIDDEN,
                    acc, xv, nullptr, NV, HIDDEN, 256, /*mode=*/3);

        // LN
        {
            int wpb = 8;
            dim3 g((NV + wpb - 1) / wpb);
            k_layernorm<<<g, wpb * 32>>>(acc, ln_g + (size_t)l * HIDDEN,
                                         ln_b + (size_t)l * HIDDEN, xv, NV);
        }

        // FFN
        launch_gemm(xv, ffn_w1 + (size_t)l * HIDDEN * 4 * HIDDEN,
                    ffn_b1 + (size_t)l * 4 * HIDDEN, h1, nullptr, nullptr,
                    NV, 4 * HIDDEN, HIDDEN, 2);
        launch_gemm(h1, ffn_w2 + (size_t)l * 4 * HIDDEN * HIDDEN,
                    ffn_b2 + (size_t)l * HIDDEN, xv, nullptr,
                    (l == LAYERS - 1) ? (float*)d_out : nullptr,
                    NV, HIDDEN, 4 * HIDDEN, 1);
    }
}